// round 12
// baseline (speedup 1.0000x reference)
#include <cuda_runtime.h>
#include <cuda_bf16.h>
#include <cstdint>

#define PB 2
#define PS 2048
#define PD 2048
#define PH 16
#define PHD 128

typedef unsigned short u16;

// Scratch (device globals: allocation-free), bf16 raw
__device__ u16 g_x_hi[(size_t)PB * PS * PD];
__device__ u16 g_x_lo[(size_t)PB * PS * PD];
__device__ u16 g_wqkv_hi[(size_t)PD * 3 * PD];
__device__ u16 g_wqkv_lo[(size_t)PD * 3 * PD];
__device__ u16 g_wout_hi[(size_t)PD * PD];
__device__ u16 g_wout_lo[(size_t)PD * PD];
__device__ u16 g_qkv_hi[(size_t)PB * PS * 3 * PD];
__device__ u16 g_qkv_lo[(size_t)PB * PS * 3 * PD];
__device__ u16 g_att_hi[(size_t)PB * PS * PD];
__device__ u16 g_att_lo[(size_t)PB * PS * PD];

// ============================ helpers ======================================
__device__ __forceinline__ uint32_t smem_u32(const void* p) {
    uint32_t a;
    asm("{ .reg .u64 t; cvta.to.shared.u64 t, %1; cvt.u32.u64 %0, t; }"
        : "=r"(a) : "l"(p));
    return a;
}
__device__ __forceinline__ void ldm_x4(uint32_t* r, uint32_t addr) {
    asm volatile("ldmatrix.sync.aligned.m8n8.x4.shared.b16 {%0,%1,%2,%3}, [%4];"
                 : "=r"(r[0]), "=r"(r[1]), "=r"(r[2]), "=r"(r[3]) : "r"(addr));
}
__device__ __forceinline__ void ldm_x4_t(uint32_t* r, uint32_t addr) {
    asm volatile("ldmatrix.sync.aligned.m8n8.x4.trans.shared.b16 {%0,%1,%2,%3}, [%4];"
                 : "=r"(r[0]), "=r"(r[1]), "=r"(r[2]), "=r"(r[3]) : "r"(addr));
}
__device__ __forceinline__ void mma_bf16(float* d, const uint32_t* a, const uint32_t* b) {
    asm volatile(
        "mma.sync.aligned.m16n8k16.row.col.f32.bf16.bf16.f32 "
        "{%0,%1,%2,%3}, {%4,%5,%6,%7}, {%8,%9}, {%0,%1,%2,%3};"
        : "+f"(d[0]), "+f"(d[1]), "+f"(d[2]), "+f"(d[3])
        : "r"(a[0]), "r"(a[1]), "r"(a[2]), "r"(a[3]), "r"(b[0]), "r"(b[1]));
}
__device__ __forceinline__ uint32_t pack2(__nv_bfloat16 x, __nv_bfloat16 y) {
    uint16_t xr = *reinterpret_cast<uint16_t*>(&x);
    uint16_t yr = *reinterpret_cast<uint16_t*>(&y);
    return (uint32_t)xr | ((uint32_t)yr << 16);
}
__device__ __forceinline__ void split4(float4 v, uint2& hi, uint2& lo) {
    __nv_bfloat16 h0 = __float2bfloat16(v.x), h1 = __float2bfloat16(v.y);
    __nv_bfloat16 h2 = __float2bfloat16(v.z), h3 = __float2bfloat16(v.w);
    float r0 = v.x - __bfloat162float(h0);
    float r1 = v.y - __bfloat162float(h1);
    float r2 = v.z - __bfloat162float(h2);
    float r3 = v.w - __bfloat162float(h3);
    hi = make_uint2(pack2(h0, h1), pack2(h2, h3));
    lo = make_uint2(pack2(__float2bfloat16(r0), __float2bfloat16(r1)),
                    pack2(__float2bfloat16(r2), __float2bfloat16(r3)));
}
__device__ __forceinline__ void packhl(float x, float y, uint32_t& hi, uint32_t& lo) {
    __nv_bfloat16 hx = __float2bfloat16(x), hy = __float2bfloat16(y);
    hi = pack2(hx, hy);
    lo = pack2(__float2bfloat16(x - __bfloat162float(hx)),
               __float2bfloat16(y - __bfloat162float(hy)));
}
__device__ __forceinline__ void cp16(uint32_t saddr, const void* gaddr) {
    asm volatile("cp.async.cg.shared.global [%0], [%1], 16;"
                 :: "r"(saddr), "l"(gaddr) : "memory");
}
#define CP_COMMIT() asm volatile("cp.async.commit_group;" ::: "memory")
#define CP_WAIT(n)  asm volatile("cp.async.wait_group %0;" :: "n"(n) : "memory")

// ===================== fp32 -> bf16 hi/lo split ===========================
__global__ void __launch_bounds__(256) split_kernel(
    const float* __restrict__ in, u16* __restrict__ hi, u16* __restrict__ lo)
{
    const size_t i = ((size_t)blockIdx.x * 256 + threadIdx.x) * 4;
    float4 v = *(const float4*)(in + i);
    uint2 h, l;
    split4(v, h, l);
    *(uint2*)&hi[i] = h;
    *(uint2*)&lo[i] = l;
}

// =============== bf16x3 GEMM (BN=128, 3-stage, 2 blk/SM) ==================
#define AROW2 80
#define BROW2 272
#define ATILE2 (128 * AROW2)
#define BTILE2 (32 * BROW2)
#define STAGE2 (2 * ATILE2 + 2 * BTILE2)   // 37888
#define GK2_SMEM (3 * STAGE2)              // 113664

template <bool SPLIT_OUT>
__global__ void __launch_bounds__(256, 2) gemm_pre(
    const u16* __restrict__ Ahi_g, const u16* __restrict__ Alo_g,
    const u16* __restrict__ Bhi_g, const u16* __restrict__ Blo_g,
    const float* __restrict__ bias, float* __restrict__ C,
    u16* __restrict__ Chi, u16* __restrict__ Clo,
    int M, int N, int K)
{
    extern __shared__ char smc[];
    const uint32_t sb = smem_u32(smc);
    const int tid = threadIdx.x, lane = tid & 31, wid = tid >> 5;
    const int row0 = blockIdx.y * 128, col0 = blockIdx.x * 128;
    const int m0 = (wid & 3) * 32, n0 = (wid >> 2) * 64;
    const int g = lane >> 3, lr = lane & 7;

    float acc[2][8][4];
    #pragma unroll
    for (int i = 0; i < 2; i++)
        #pragma unroll
        for (int j = 0; j < 8; j++)
            #pragma unroll
            for (int q = 0; q < 4; q++) acc[i][j][q] = 0.f;

    auto LOADC = [&](int kc, int s) {
        const uint32_t sa = sb + (uint32_t)s * STAGE2;
        #pragma unroll
        for (int it = 0; it < 2; it++) {
            int e = tid + it * 256;
            int r = e >> 2, c16 = e & 3;
            uint32_t off = sa + r * AROW2 + c16 * 16;
            size_t gi = (size_t)(row0 + r) * K + kc + c16 * 8;
            cp16(off, Ahi_g + gi);
            cp16(off + ATILE2, Alo_g + gi);
        }
        #pragma unroll
        for (int it = 0; it < 2; it++) {
            int e = tid + it * 256;
            int k = e >> 4, c16 = e & 15;
            uint32_t off = sa + 2 * ATILE2 + k * BROW2 + c16 * 16;
            size_t gi = (size_t)(kc + k) * N + col0 + c16 * 8;
            cp16(off, Bhi_g + gi);
            cp16(off + BTILE2, Blo_g + gi);
        }
        CP_COMMIT();
    };

    auto MMAC = [&](int s) {
        const uint32_t Ah = sb + (uint32_t)s * STAGE2;
        const uint32_t Bh = Ah + 2 * ATILE2;
        #pragma unroll
        for (int ks = 0; ks < 2; ks++) {
            const int kb = ks * 16;
            uint32_t aH[2][4], aL[2][4];
            #pragma unroll
            for (int mt = 0; mt < 2; mt++) {
                uint32_t ad = Ah + (m0 + mt * 16 + lr + ((g & 1) << 3)) * AROW2
                                 + (kb + ((g >> 1) << 3)) * 2;
                ldm_x4(aH[mt], ad);
                ldm_x4(aL[mt], ad + ATILE2);
            }
            #pragma unroll
            for (int q = 0; q < 4; q++) {
                int kk = kb + lr + ((g & 1) << 3);
                uint32_t bd = Bh + kk * BROW2 + (n0 + q * 16 + ((g >> 1) << 3)) * 2;
                uint32_t tH[4], tL[4];
                ldm_x4_t(tH, bd);
                ldm_x4_t(tL, bd + BTILE2);
                #pragma unroll
                for (int mt = 0; mt < 2; mt++) {
                    mma_bf16(acc[mt][2 * q],     aH[mt], tH);
                    mma_bf16(acc[mt][2 * q + 1], aH[mt], tH + 2);
                    mma_bf16(acc[mt][2 * q],     aH[mt], tL);
                    mma_bf16(acc[mt][2 * q + 1], aH[mt], tL + 2);
                    mma_bf16(acc[mt][2 * q],     aL[mt], tH);
                    mma_bf16(acc[mt][2 * q + 1], aL[mt], tH + 2);
                }
            }
        }
    };

    const int NCH = K >> 5;

    LOADC(0, 0);
    LOADC(32, 1);

    int s = 0;
    int sn = 2;
    for (int c = 0; c < NCH; c++) {
        if (c + 1 < NCH) { CP_WAIT(1); } else { CP_WAIT(0); }
        __syncthreads();
        if (c + 2 < NCH) LOADC((c + 2) << 5, sn);
        MMAC(s);
        s = (s == 2) ? 0 : s + 1;
        sn = (sn == 2) ? 0 : sn + 1;
    }

    #pragma unroll
    for (int mt = 0; mt < 2; mt++) {
        #pragma unroll
        for (int nt = 0; nt < 8; nt++) {
            const int r = row0 + m0 + mt * 16 + (lane >> 2);
            const int cc = col0 + n0 + nt * 8 + ((lane & 3) << 1);
            const float b0 = bias[cc], b1 = bias[cc + 1];
            float v00 = acc[mt][nt][0] + b0, v01 = acc[mt][nt][1] + b1;
            float v10 = acc[mt][nt][2] + b0, v11 = acc[mt][nt][3] + b1;
            if (SPLIT_OUT) {
                uint32_t h, l;
                packhl(v00, v01, h, l);
                *(uint32_t*)&Chi[(size_t)r * N + cc] = h;
                *(uint32_t*)&Clo[(size_t)r * N + cc] = l;
                packhl(v10, v11, h, l);
                *(uint32_t*)&Chi[(size_t)(r + 8) * N + cc] = h;
                *(uint32_t*)&Clo[(size_t)(r + 8) * N + cc] = l;
            } else {
                *(float2*)(C + (size_t)r * N + cc) = make_float2(v00, v01);
                *(float2*)(C + (size_t)(r + 8) * N + cc) = make_float2(v10, v11);
            }
        }
    }
}

// ====== Flash attention, bf16x3, double-buffered K/V, Q-in-registers ======
#define BQ 128
#define BK 64
#define TROW 272
#define QTILE (128 * TROW)                 // 34816
#define KTILE (64 * TROW)                  // 17408
#define KVSTG (4 * KTILE)                  // 69632
#define AT_SMEM (2 * QTILE + 2 * KVSTG)    // 208896, 1 block/SM

__global__ void __launch_bounds__(256, 1) attn_mma(
    const u16* __restrict__ qkv_hi, const u16* __restrict__ qkv_lo,
    u16* __restrict__ att_hi, u16* __restrict__ att_lo)
{
    extern __shared__ char smc[];
    const uint32_t sb = smem_u32(smc);
    const uint32_t sQhi = sb;
    const uint32_t sKV  = sb + 2 * QTILE;

    const int qt = (int)gridDim.x - 1 - (int)blockIdx.x;
    const int bh = blockIdx.y;
    const int b  = bh >> 4;
    const int h  = bh & 15;
    const int q0 = qt * BQ;
    const int tid  = threadIdx.x;
    const int lane = tid & 31;
    const int wid  = tid >> 5;
    const int lr   = lane & 7;
    const int g    = lane >> 3;
    const int rl   = lane >> 2;
    const int cq   = (lane & 3) << 1;

    const size_t rs = 3 * PD;
    const size_t base = (size_t)b * PS * rs + (size_t)h * PHD;
    const u16* qh = qkv_hi + base;
    const u16* ql = qkv_lo + base;
    const u16* kh = qh + PD;
    const u16* kl = ql + PD;
    const u16* vh = qh + 2 * PD;
    const u16* vl = ql + 2 * PD;

    auto load_kv = [&](int kt, int st) {
        const uint32_t sa = sKV + (uint32_t)st * KVSTG;
        const int k0 = kt * BK;
        #pragma unroll
        for (int it = 0; it < 4; it++) {
            int e = tid + it * 256;
            int r = e >> 4, c16 = e & 15;
            uint32_t koff = sa + r * TROW + c16 * 16;
            uint32_t voff = koff + 2 * KTILE;
            size_t gi = (size_t)(k0 + r) * rs + c16 * 8;
            cp16(koff, kh + gi);
            cp16(koff + KTILE, kl + gi);
            cp16(voff, vh + gi);
            cp16(voff + KTILE, vl + gi);
        }
        CP_COMMIT();
    };

    // Q tile (hi+lo), one commit group
    #pragma unroll
    for (int it = 0; it < 8; it++) {
        int e = tid + it * 256;
        int r = e >> 4, c16 = e & 15;
        uint32_t off = sQhi + r * TROW + c16 * 16;
        size_t gi = (size_t)(q0 + r) * rs + c16 * 8;
        cp16(off, qh + gi);
        cp16(off + QTILE, ql + gi);
    }
    CP_COMMIT();

    load_kv(0, 0);      // prefetch tile 0 (stays in flight past the Q wait)

    // ---- Q fragments -> registers (once); Q smem read-only dead after this
    CP_WAIT(1);         // Q group landed
    __syncthreads();
    uint32_t qH[8][4], qL[8][4];
    #pragma unroll
    for (int ks = 0; ks < 8; ks++) {
        const uint32_t ad = sQhi + (wid * 16 + lr + ((g & 1) << 3)) * TROW
                                 + (ks * 16 + ((g >> 1) << 3)) * 2;
        ldm_x4(qH[ks], ad);
        ldm_x4(qL[ks], ad + QTILE);
    }

    float O[16][4];
    #pragma unroll
    for (int nt = 0; nt < 16; nt++)
        #pragma unroll
        for (int c = 0; c < 4; c++) O[nt][c] = 0.f;
    float m0r = -1e30f, m1r = -1e30f, l0r = 0.f, l1r = 0.f;
    const float scale = 0.08838834764831845f;
    const int row_g0 = q0 + wid * 16 + rl;
    const int row_g1 = row_g0 + 8;

    const int nkt = 2 * qt + 2;
    for (int kt = 0; kt < nkt; kt++) {
        const int k0 = kt * BK;
        const int cur = kt & 1;
        if (kt + 1 < nkt) {
            load_kv(kt + 1, cur ^ 1);
            CP_WAIT(1);
        } else {
            CP_WAIT(0);
        }
        __syncthreads();

        const uint32_t sKhi = sKV + (uint32_t)cur * KVSTG;
        const uint32_t sVhi = sKhi + 2 * KTILE;

        // ---- S = Q K^T (3-term), Q from registers
        float S[8][4];
        #pragma unroll
        for (int j = 0; j < 8; j++)
            #pragma unroll
            for (int c = 0; c < 4; c++) S[j][c] = 0.f;

        #pragma unroll
        for (int ks = 0; ks < 8; ks++) {
            #pragma unroll
            for (int p = 0; p < 4; p++) {
                uint32_t kH[4], kL[4];
                const uint32_t kd = sKhi + (p * 16 + lr + ((g >> 1) << 3)) * TROW
                                         + (ks * 16 + ((g & 1) << 3)) * 2;
                ldm_x4(kH, kd);
                ldm_x4(kL, kd + KTILE);
                mma_bf16(S[2 * p],     qH[ks], kH);
                mma_bf16(S[2 * p + 1], qH[ks], kH + 2);
                mma_bf16(S[2 * p],     qH[ks], kL);
                mma_bf16(S[2 * p + 1], qH[ks], kL + 2);
                mma_bf16(S[2 * p],     qL[ks], kH);
                mma_bf16(S[2 * p + 1], qL[ks], kH + 2);
            }
        }

        // ---- scale + mask + online softmax
        const bool need_mask = (k0 + BK - 1 > q0);
        float mx0 = -1e30f, mx1 = -1e30f;
        #pragma unroll
        for (int j = 0; j < 8; j++) {
            #pragma unroll
            for (int c = 0; c < 4; c++) {
                float s = S[j][c] * scale;
                if (need_mask) {
                    const int col = k0 + j * 8 + cq + (c & 1);
                    const int row = (c < 2) ? row_g0 : row_g1;
                    if (col > row) s = -1e30f;
                }
                S[j][c] = s;
            }
            mx0 = fmaxf(mx0, fmaxf(S[j][0], S[j][1]));
            mx1 = fmaxf(mx1, fmaxf(S[j][2], S[j][3]));
        }
        #pragma unroll
        for (int off = 1; off <= 2; off <<= 1) {
            mx0 = fmaxf(mx0, __shfl_xor_sync(0xffffffffu, mx0, off));
            mx1 = fmaxf(mx1, __shfl_xor_sync(0xffffffffu, mx1, off));
        }
        const float nm0 = fmaxf(m0r, mx0), nm1 = fmaxf(m1r, mx1);
        const float al0 = __expf(m0r - nm0), al1 = __expf(m1r - nm1);
        float sum0 = 0.f, sum1 = 0.f;
        #pragma unroll
        for (int j = 0; j < 8; j++) {
            S[j][0] = __expf(S[j][0] - nm0);
            S[j][1] = __expf(S[j][1] - nm0);
            S[j][2] = __expf(S[j][2] - nm1);
            S[j][3] = __expf(S[j][3] - nm1);
            sum0 += S[j][0] + S[j][1];
            sum1 += S[j][2] + S[j][3];
        }
        #pragma unroll
        for (int off = 1; off <= 2; off <<= 1) {
            sum0 += __shfl_xor_sync(0xffffffffu, sum0, off);
            sum1 += __shfl_xor_sync(0xffffffffu, sum1, off);
        }
        l0r = l0r * al0 + sum0;
        l1r = l1r * al1 + sum1;
        m0r = nm0; m1r = nm1;
        #pragma unroll
        for (int nt = 0; nt < 16; nt++) {
            O[nt][0] *= al0; O[nt][1] *= al0;
            O[nt][2] *= al1; O[nt][3] *= al1;
        }

        // ---- O += P V (3-term)
        #pragma unroll
        for (int kk = 0; kk < 4; kk++) {
            uint32_t aPh[4], aPl[4];
            const int j0 = 2 * kk, j1 = 2 * kk + 1;
            packhl(S[j0][0], S[j0][1], aPh[0], aPl[0]);
            packhl(S[j0][2], S[j0][3], aPh[1], aPl[1]);
            packhl(S[j1][0], S[j1][1], aPh[2], aPl[2]);
            packhl(S[j1][2], S[j1][3], aPh[3], aPl[3]);
            #pragma unroll
            for (int nq = 0; nq < 4; nq++) {
                uint32_t vH0[4], vL0[4], vH1[4], vL1[4];
                const uint32_t vd0 = sVhi + (kk * 16 + lr + ((g & 1) << 3)) * TROW
                                          + ((2 * nq) * 16 + ((g >> 1) << 3)) * 2;
                const uint32_t vd1 = vd0 + 32;
                ldm_x4_t(vH0, vd0);
                ldm_x4_t(vL0, vd0 + KTILE);
                ldm_x4_t(vH1, vd1);
                ldm_x4_t(vL1, vd1 + KTILE);
                float* o0 = O[4 * nq];
                float* o1 = O[4 * nq + 1];
                float* o2 = O[4 * nq + 2];
                float* o3 = O[4 * nq + 3];
                mma_bf16(o0, aPh, vH0);
                mma_bf16(o1, aPh, vH0 + 2);
                mma_bf16(o2, aPh, vH1);
                mma_bf16(o3, aPh, vH1 + 2);
                mma_bf16(o0, aPh, vL0);
                mma_bf16(o1, aPh, vL0 + 2);
                mma_bf16(o2, aPh, vL1);
                mma_bf16(o3, aPh, vL1 + 2);
                mma_bf16(o0, aPl, vH0);
                mma_bf16(o1, aPl, vH0 + 2);
                mma_bf16(o2, aPl, vH1);
                mma_bf16(o3, aPl, vH1 + 2);
            }
        }
        __syncthreads();   // stage `cur` fully consumed before reload
    }

    // ---- normalize + split-write O
    const float inv0 = 1.f / l0r, inv1 = 1.f / l1r;
    const size_t o0 = ((size_t)b * PS + row_g0) * PD + h * PHD;
    const size_t o1 = ((size_t)b * PS + row_g1) * PD + h * PHD;
    #pragma unroll
    for (int nt = 0; nt < 16; nt++) {
        const int col = nt * 8 + cq;
        uint32_t hh, ll;
        packhl(O[nt][0] * inv0, O[nt][1] * inv0, hh, ll);
        *(uint32_t*)&att_hi[o0 + col] = hh;
        *(uint32_t*)&att_lo[o0 + col] = ll;
        packhl(O[nt][2] * inv1, O[nt][3] * inv1, hh, ll);
        *(uint32_t*)&att_hi[o1 + col] = hh;
        *(uint32_t*)&att_lo[o1 + col] = ll;
    }
}

// ---------------------------------------------------------------------------
extern "C" void kernel_launch(void* const* d_in, const int* in_sizes, int n_in,
                              void* d_out, int out_size)
{
    const float* x     = (const float*)d_in[0];
    const float* w_qkv = (const float*)d_in[1];
    const float* b_qkv = (const float*)d_in[2];
    const float* w_out = (const float*)d_in[3];
    const float* b_out = (const float*)d_in[4];
    float* out = (float*)d_out;

    u16 *x_hi, *x_lo, *wq_hi, *wq_lo, *wo_hi, *wo_lo, *qk_hi, *qk_lo, *at_hi, *at_lo;
    cudaGetSymbolAddress((void**)&x_hi,  g_x_hi);
    cudaGetSymbolAddress((void**)&x_lo,  g_x_lo);
    cudaGetSymbolAddress((void**)&wq_hi, g_wqkv_hi);
    cudaGetSymbolAddress((void**)&wq_lo, g_wqkv_lo);
    cudaGetSymbolAddress((void**)&wo_hi, g_wout_hi);
    cudaGetSymbolAddress((void**)&wo_lo, g_wout_lo);
    cudaGetSymbolAddress((void**)&qk_hi, g_qkv_hi);
    cudaGetSymbolAddress((void**)&qk_lo, g_qkv_lo);
    cudaGetSymbolAddress((void**)&at_hi, g_att_hi);
    cudaGetSymbolAddress((void**)&at_lo, g_att_lo);

    cudaFuncSetAttribute(gemm_pre<true>,
                         cudaFuncAttributeMaxDynamicSharedMemorySize, GK2_SMEM);
    cudaFuncSetAttribute(gemm_pre<false>,
                         cudaFuncAttributeMaxDynamicSharedMemorySize, GK2_SMEM);
    cudaFuncSetAttribute(attn_mma,
                         cudaFuncAttributeMaxDynamicSharedMemorySize, AT_SMEM);

    split_kernel<<<(PB * PS * PD) / 1024, 256>>>(x, x_hi, x_lo);
    split_kernel<<<(PD * 3 * PD) / 1024, 256>>>(w_qkv, wq_hi, wq_lo);
    split_kernel<<<(PD * PD) / 1024, 256>>>(w_out, wo_hi, wo_lo);

    gemm_pre<true><<<dim3(6144 / 128, 4096 / 128), 256, GK2_SMEM>>>(
        x_hi, x_lo, wq_hi, wq_lo, b_qkv, nullptr, qk_hi, qk_lo,
        PB * PS, 3 * PD, PD);
    attn_mma<<<dim3(PS / BQ, PB * PH), 256, AT_SMEM>>>(qk_hi, qk_lo, at_hi, at_lo);
    gemm_pre<false><<<dim3(2048 / 128, 4096 / 128), 256, GK2_SMEM>>>(
        at_hi, at_lo, wo_hi, wo_lo, b_out, out, nullptr, nullptr,
        PB * PS, PD, PD);
}

// round 14
// speedup vs baseline: 1.0066x; 1.0066x over previous
#include <cuda_runtime.h>
#include <cuda_bf16.h>
#include <cstdint>

#define PB 2
#define PS 2048
#define PD 2048
#define PH 16
#define PHD 128

typedef unsigned short u16;

// Scratch (device globals: allocation-free), bf16 raw
__device__ u16 g_x_hi[(size_t)PB * PS * PD];
__device__ u16 g_x_lo[(size_t)PB * PS * PD];
__device__ u16 g_wqkv_hi[(size_t)PD * 3 * PD];
__device__ u16 g_wqkv_lo[(size_t)PD * 3 * PD];
__device__ u16 g_wout_hi[(size_t)PD * PD];
__device__ u16 g_wout_lo[(size_t)PD * PD];
__device__ u16 g_qkv_hi[(size_t)PB * PS * 3 * PD];
__device__ u16 g_qkv_lo[(size_t)PB * PS * 3 * PD];
__device__ u16 g_att_hi[(size_t)PB * PS * PD];
__device__ u16 g_att_lo[(size_t)PB * PS * PD];

// ============================ helpers ======================================
__device__ __forceinline__ uint32_t smem_u32(const void* p) {
    uint32_t a;
    asm("{ .reg .u64 t; cvta.to.shared.u64 t, %1; cvt.u32.u64 %0, t; }"
        : "=r"(a) : "l"(p));
    return a;
}
__device__ __forceinline__ void ldm_x4(uint32_t* r, uint32_t addr) {
    asm volatile("ldmatrix.sync.aligned.m8n8.x4.shared.b16 {%0,%1,%2,%3}, [%4];"
                 : "=r"(r[0]), "=r"(r[1]), "=r"(r[2]), "=r"(r[3]) : "r"(addr));
}
__device__ __forceinline__ void ldm_x4_t(uint32_t* r, uint32_t addr) {
    asm volatile("ldmatrix.sync.aligned.m8n8.x4.trans.shared.b16 {%0,%1,%2,%3}, [%4];"
                 : "=r"(r[0]), "=r"(r[1]), "=r"(r[2]), "=r"(r[3]) : "r"(addr));
}
__device__ __forceinline__ void mma_bf16(float* d, const uint32_t* a, const uint32_t* b) {
    asm volatile(
        "mma.sync.aligned.m16n8k16.row.col.f32.bf16.bf16.f32 "
        "{%0,%1,%2,%3}, {%4,%5,%6,%7}, {%8,%9}, {%0,%1,%2,%3};"
        : "+f"(d[0]), "+f"(d[1]), "+f"(d[2]), "+f"(d[3])
        : "r"(a[0]), "r"(a[1]), "r"(a[2]), "r"(a[3]), "r"(b[0]), "r"(b[1]));
}
__device__ __forceinline__ uint32_t pack2(__nv_bfloat16 x, __nv_bfloat16 y) {
    uint16_t xr = *reinterpret_cast<uint16_t*>(&x);
    uint16_t yr = *reinterpret_cast<uint16_t*>(&y);
    return (uint32_t)xr | ((uint32_t)yr << 16);
}
__device__ __forceinline__ void split4(float4 v, uint2& hi, uint2& lo) {
    __nv_bfloat16 h0 = __float2bfloat16(v.x), h1 = __float2bfloat16(v.y);
    __nv_bfloat16 h2 = __float2bfloat16(v.z), h3 = __float2bfloat16(v.w);
    float r0 = v.x - __bfloat162float(h0);
    float r1 = v.y - __bfloat162float(h1);
    float r2 = v.z - __bfloat162float(h2);
    float r3 = v.w - __bfloat162float(h3);
    hi = make_uint2(pack2(h0, h1), pack2(h2, h3));
    lo = make_uint2(pack2(__float2bfloat16(r0), __float2bfloat16(r1)),
                    pack2(__float2bfloat16(r2), __float2bfloat16(r3)));
}
__device__ __forceinline__ void packhl(float x, float y, uint32_t& hi, uint32_t& lo) {
    __nv_bfloat16 hx = __float2bfloat16(x), hy = __float2bfloat16(y);
    hi = pack2(hx, hy);
    lo = pack2(__float2bfloat16(x - __bfloat162float(hx)),
               __float2bfloat16(y - __bfloat162float(hy)));
}
__device__ __forceinline__ void cp16(uint32_t saddr, const void* gaddr) {
    asm volatile("cp.async.cg.shared.global [%0], [%1], 16;"
                 :: "r"(saddr), "l"(gaddr) : "memory");
}
#define CP_COMMIT() asm volatile("cp.async.commit_group;" ::: "memory")
#define CP_WAIT(n)  asm volatile("cp.async.wait_group %0;" :: "n"(n) : "memory")

// ============ fused fp32 -> bf16 hi/lo split (3 tensors, 1 launch) ========
#define XB   ((PB * PS * PD) / 1024)          // 8192 blocks
#define WQB  ((PD * 3 * PD) / 1024)           // 12288 blocks
#define WOB  ((PD * PD) / 1024)               // 4096 blocks

__global__ void __launch_bounds__(256) split_all(
    const float* __restrict__ x,   u16* __restrict__ xh,  u16* __restrict__ xl,
    const float* __restrict__ wq,  u16* __restrict__ wqh, u16* __restrict__ wql,
    const float* __restrict__ wo,  u16* __restrict__ woh, u16* __restrict__ wol)
{
    int bid = blockIdx.x;
    const float* in;
    u16 *hi, *lo;
    if (bid < XB) { in = x; hi = xh; lo = xl; }
    else if (bid < XB + WQB) { bid -= XB; in = wq; hi = wqh; lo = wql; }
    else { bid -= XB + WQB; in = wo; hi = woh; lo = wol; }
    const size_t i = ((size_t)bid * 256 + threadIdx.x) * 4;
    float4 v = *(const float4*)(in + i);
    uint2 h, l;
    split4(v, h, l);
    *(uint2*)&hi[i] = h;
    *(uint2*)&lo[i] = l;
}

// =============== bf16x3 GEMM (BN=128, 3-stage, 2 blk/SM) ==================
#define AROW2 80
#define BROW2 272
#define ATILE2 (128 * AROW2)
#define BTILE2 (32 * BROW2)
#define STAGE2 (2 * ATILE2 + 2 * BTILE2)   // 37888
#define GK2_SMEM (3 * STAGE2)              // 113664

template <bool SPLIT_OUT>
__global__ void __launch_bounds__(256, 2) gemm_pre(
    const u16* __restrict__ Ahi_g, const u16* __restrict__ Alo_g,
    const u16* __restrict__ Bhi_g, const u16* __restrict__ Blo_g,
    const float* __restrict__ bias, float* __restrict__ C,
    u16* __restrict__ Chi, u16* __restrict__ Clo,
    int M, int N, int K)
{
    extern __shared__ char smc[];
    const uint32_t sb = smem_u32(smc);
    const int tid = threadIdx.x, lane = tid & 31, wid = tid >> 5;
    const int row0 = blockIdx.y * 128, col0 = blockIdx.x * 128;
    const int m0 = (wid & 3) * 32, n0 = (wid >> 2) * 64;
    const int g = lane >> 3, lr = lane & 7;

    float acc[2][8][4];
    #pragma unroll
    for (int i = 0; i < 2; i++)
        #pragma unroll
        for (int j = 0; j < 8; j++)
            #pragma unroll
            for (int q = 0; q < 4; q++) acc[i][j][q] = 0.f;

    auto LOADC = [&](int kc, int s) {
        const uint32_t sa = sb + (uint32_t)s * STAGE2;
        #pragma unroll
        for (int it = 0; it < 2; it++) {
            int e = tid + it * 256;
            int r = e >> 2, c16 = e & 3;
            uint32_t off = sa + r * AROW2 + c16 * 16;
            size_t gi = (size_t)(row0 + r) * K + kc + c16 * 8;
            cp16(off, Ahi_g + gi);
            cp16(off + ATILE2, Alo_g + gi);
        }
        #pragma unroll
        for (int it = 0; it < 2; it++) {
            int e = tid + it * 256;
            int k = e >> 4, c16 = e & 15;
            uint32_t off = sa + 2 * ATILE2 + k * BROW2 + c16 * 16;
            size_t gi = (size_t)(kc + k) * N + col0 + c16 * 8;
            cp16(off, Bhi_g + gi);
            cp16(off + BTILE2, Blo_g + gi);
        }
        CP_COMMIT();
    };

    auto MMAC = [&](int s) {
        const uint32_t Ah = sb + (uint32_t)s * STAGE2;
        const uint32_t Bh = Ah + 2 * ATILE2;
        #pragma unroll
        for (int ks = 0; ks < 2; ks++) {
            const int kb = ks * 16;
            uint32_t aH[2][4], aL[2][4];
            #pragma unroll
            for (int mt = 0; mt < 2; mt++) {
                uint32_t ad = Ah + (m0 + mt * 16 + lr + ((g & 1) << 3)) * AROW2
                                 + (kb + ((g >> 1) << 3)) * 2;
                ldm_x4(aH[mt], ad);
                ldm_x4(aL[mt], ad + ATILE2);
            }
            #pragma unroll
            for (int q = 0; q < 4; q++) {
                int kk = kb + lr + ((g & 1) << 3);
                uint32_t bd = Bh + kk * BROW2 + (n0 + q * 16 + ((g >> 1) << 3)) * 2;
                uint32_t tH[4], tL[4];
                ldm_x4_t(tH, bd);
                ldm_x4_t(tL, bd + BTILE2);
                #pragma unroll
                for (int mt = 0; mt < 2; mt++) {
                    mma_bf16(acc[mt][2 * q],     aH[mt], tH);
                    mma_bf16(acc[mt][2 * q + 1], aH[mt], tH + 2);
                    mma_bf16(acc[mt][2 * q],     aH[mt], tL);
                    mma_bf16(acc[mt][2 * q + 1], aH[mt], tL + 2);
                    mma_bf16(acc[mt][2 * q],     aL[mt], tH);
                    mma_bf16(acc[mt][2 * q + 1], aL[mt], tH + 2);
                }
            }
        }
    };

    const int NCH = K >> 5;

    LOADC(0, 0);
    LOADC(32, 1);

    int s = 0;
    int sn = 2;
    for (int c = 0; c < NCH; c++) {
        if (c + 1 < NCH) { CP_WAIT(1); } else { CP_WAIT(0); }
        __syncthreads();
        if (c + 2 < NCH) LOADC((c + 2) << 5, sn);
        MMAC(s);
        s = (s == 2) ? 0 : s + 1;
        sn = (sn == 2) ? 0 : sn + 1;
    }

    #pragma unroll
    for (int mt = 0; mt < 2; mt++) {
        #pragma unroll
        for (int nt = 0; nt < 8; nt++) {
            const int r = row0 + m0 + mt * 16 + (lane >> 2);
            const int cc = col0 + n0 + nt * 8 + ((lane & 3) << 1);
            const float b0 = bias[cc], b1 = bias[cc + 1];
            float v00 = acc[mt][nt][0] + b0, v01 = acc[mt][nt][1] + b1;
            float v10 = acc[mt][nt][2] + b0, v11 = acc[mt][nt][3] + b1;
            if (SPLIT_OUT) {
                uint32_t h, l;
                packhl(v00, v01, h, l);
                *(uint32_t*)&Chi[(size_t)r * N + cc] = h;
                *(uint32_t*)&Clo[(size_t)r * N + cc] = l;
                packhl(v10, v11, h, l);
                *(uint32_t*)&Chi[(size_t)(r + 8) * N + cc] = h;
                *(uint32_t*)&Clo[(size_t)(r + 8) * N + cc] = l;
            } else {
                *(float2*)(C + (size_t)r * N + cc) = make_float2(v00, v01);
                *(float2*)(C + (size_t)(r + 8) * N + cc) = make_float2(v10, v11);
            }
        }
    }
}

// == Flash attention: Q-in-regs, 3-stage KV ring (recycled Q smem), 1 bar ==
#define BQ 128
#define BK 64
#define TROW 272
#define KTILE (64 * TROW)                  // 17408
#define KVSTG (4 * KTILE)                  // 69632: Khi,Klo,Vhi,Vlo
#define AT_SMEM (3 * KVSTG)                // 208896; stage2 doubles as Q landing

__global__ void __launch_bounds__(256, 1) attn_mma(
    const u16* __restrict__ qkv_hi, const u16* __restrict__ qkv_lo,
    u16* __restrict__ att_hi, u16* __restrict__ att_lo)
{
    extern __shared__ char smc[];
    const uint32_t sb = smem_u32(smc);
    const uint32_t sKV = sb;                       // 3 stages of KVSTG
    const uint32_t sQ  = sb + 2 * KVSTG;           // Q lands in stage 2

    const int qt = (int)gridDim.x - 1 - (int)blockIdx.x;
    const int bh = blockIdx.y;
    const int b  = bh >> 4;
    const int h  = bh & 15;
    const int q0 = qt * BQ;
    const int tid  = threadIdx.x;
    const int lane = tid & 31;
    const int wid  = tid >> 5;
    const int lr   = lane & 7;
    const int g    = lane >> 3;
    const int rl   = lane >> 2;
    const int cq   = (lane & 3) << 1;

    const size_t rs = 3 * PD;
    const size_t base = (size_t)b * PS * rs + (size_t)h * PHD;
    const u16* qh = qkv_hi + base;
    const u16* ql = qkv_lo + base;
    const u16* kh = qh + PD;
    const u16* kl = ql + PD;
    const u16* vh = qh + 2 * PD;
    const u16* vl = ql + 2 * PD;

    auto load_kv = [&](int kt, int st) {
        const uint32_t sa = sKV + (uint32_t)st * KVSTG;
        const int k0 = kt * BK;
        #pragma unroll
        for (int it = 0; it < 4; it++) {
            int e = tid + it * 256;
            int r = e >> 4, c16 = e & 15;
            uint32_t koff = sa + r * TROW + c16 * 16;
            uint32_t voff = koff + 2 * KTILE;
            size_t gi = (size_t)(k0 + r) * rs + c16 * 8;
            cp16(koff, kh + gi);
            cp16(koff + KTILE, kl + gi);
            cp16(voff, vh + gi);
            cp16(voff + KTILE, vl + gi);
        }
        CP_COMMIT();
    };

    // Q (hi at sQ, lo at sQ + 2*KTILE): 128 rows x 16 chunks, one group
    #pragma unroll
    for (int it = 0; it < 8; it++) {
        int e = tid + it * 256;
        int r = e >> 4, c16 = e & 15;
        uint32_t off = sQ + r * TROW + c16 * 16;
        size_t gi = (size_t)(q0 + r) * rs + c16 * 8;
        cp16(off, qh + gi);
        cp16(off + 2 * KTILE, ql + gi);
    }
    CP_COMMIT();

    const int nkt = 2 * qt + 2;
    load_kv(0, 0);
    if (nkt > 1) load_kv(1, 1);

    // ---- Q fragments -> registers; stage 2 then becomes a KV stage
    CP_WAIT(2);         // Q landed (kv0/kv1 may still be in flight)
    __syncthreads();
    uint32_t qH[8][4], qL[8][4];
    #pragma unroll
    for (int ks = 0; ks < 8; ks++) {
        const uint32_t ad = sQ + (wid * 16 + lr + ((g & 1) << 3)) * TROW
                               + (ks * 16 + ((g >> 1) << 3)) * 2;
        ldm_x4(qH[ks], ad);
        ldm_x4(qL[ks], ad + 2 * KTILE);
    }
    __syncthreads();    // all warps extracted Q; stage 2 reusable

    float O[16][4];
    #pragma unroll
    for (int nt = 0; nt < 16; nt++)
        #pragma unroll
        for (int c = 0; c < 4; c++) O[nt][c] = 0.f;
    float m0r = -1e30f, m1r = -1e30f, l0r = 0.f, l1r = 0.f;
    const float scale = 0.08838834764831845f;
    const int row_g0 = q0 + wid * 16 + rl;
    const int row_g1 = row_g0 + 8;

    int st = 0;                    // stage of tile kt
    int sn = 2;                    // stage for tile kt+2
    for (int kt = 0; kt < nkt; kt++) {
        const int k0 = kt * BK;
        if (kt + 1 < nkt) { CP_WAIT(1); } else { CP_WAIT(0); }
        __syncthreads();           // all warps done with stage sn (tile kt-1)
        if (kt + 2 < nkt) load_kv(kt + 2, sn);

        const uint32_t sKhi = sKV + (uint32_t)st * KVSTG;
        const uint32_t sVhi = sKhi + 2 * KTILE;

        // ---- S = Q K^T (3-term), Q from registers
        float S[8][4];
        #pragma unroll
        for (int j = 0; j < 8; j++)
            #pragma unroll
            for (int c = 0; c < 4; c++) S[j][c] = 0.f;

        #pragma unroll
        for (int ks = 0; ks < 8; ks++) {
            #pragma unroll
            for (int p = 0; p < 4; p++) {
                uint32_t kH[4], kL[4];
                const uint32_t kd = sKhi + (p * 16 + lr + ((g >> 1) << 3)) * TROW
                                         + (ks * 16 + ((g & 1) << 3)) * 2;
                ldm_x4(kH, kd);
                ldm_x4(kL, kd + KTILE);
                mma_bf16(S[2 * p],     qH[ks], kH);
                mma_bf16(S[2 * p + 1], qH[ks], kH + 2);
                mma_bf16(S[2 * p],     qH[ks], kL);
                mma_bf16(S[2 * p + 1], qH[ks], kL + 2);
                mma_bf16(S[2 * p],     qL[ks], kH);
                mma_bf16(S[2 * p + 1], qL[ks], kH + 2);
            }
        }

        // ---- scale + mask + online softmax
        const bool need_mask = (k0 + BK - 1 > q0);
        float mx0 = -1e30f, mx1 = -1e30f;
        #pragma unroll
        for (int j = 0; j < 8; j++) {
            #pragma unroll
            for (int c = 0; c < 4; c++) {
                float s = S[j][c] * scale;
                if (need_mask) {
                    const int col = k0 + j * 8 + cq + (c & 1);
                    const int row = (c < 2) ? row_g0 : row_g1;
                    if (col > row) s = -1e30f;
                }
                S[j][c] = s;
            }
            mx0 = fmaxf(mx0, fmaxf(S[j][0], S[j][1]));
            mx1 = fmaxf(mx1, fmaxf(S[j][2], S[j][3]));
        }
        #pragma unroll
        for (int off = 1; off <= 2; off <<= 1) {
            mx0 = fmaxf(mx0, __shfl_xor_sync(0xffffffffu, mx0, off));
            mx1 = fmaxf(mx1, __shfl_xor_sync(0xffffffffu, mx1, off));
        }
        const float nm0 = fmaxf(m0r, mx0), nm1 = fmaxf(m1r, mx1);
        const float al0 = __expf(m0r - nm0), al1 = __expf(m1r - nm1);
        float sum0 = 0.f, sum1 = 0.f;
        #pragma unroll
        for (int j = 0; j < 8; j++) {
            S[j][0] = __expf(S[j][0] - nm0);
            S[j][1] = __expf(S[j][1] - nm0);
            S[j][2] = __expf(S[j][2] - nm1);
            S[j][3] = __expf(S[j][3] - nm1);
            sum0 += S[j][0] + S[j][1];
            sum1 += S[j][2] + S[j][3];
        }
        #pragma unroll
        for (int off = 1; off <= 2; off <<= 1) {
            sum0 += __shfl_xor_sync(0xffffffffu, sum0, off);
            sum1 += __shfl_xor_sync(0xffffffffu, sum1, off);
        }
        l0r = l0r * al0 + sum0;
        l1r = l1r * al1 + sum1;
        m0r = nm0; m1r = nm1;
        #pragma unroll
        for (int nt = 0; nt < 16; nt++) {
            O[nt][0] *= al0; O[nt][1] *= al0;
            O[nt][2] *= al1; O[nt][3] *= al1;
        }

        // ---- O += P V (3-term)
        #pragma unroll
        for (int kk = 0; kk < 4; kk++) {
            uint32_t aPh[4], aPl[4];
            const int j0 = 2 * kk, j1 = 2 * kk + 1;
            packhl(S[j0][0], S[j0][1], aPh[0], aPl[0]);
            packhl(S[j0][2], S[j0][3], aPh[1], aPl[1]);
            packhl(S[j1][0], S[j1][1], aPh[2], aPl[2]);
            packhl(S[j1][2], S[j1][3], aPh[3], aPl[3]);
            #pragma unroll
            for (int nq = 0; nq < 4; nq++) {
                uint32_t vH0[4], vL0[4], vH1[4], vL1[4];
                const uint32_t vd0 = sVhi + (kk * 16 + lr + ((g & 1) << 3)) * TROW
                                          + ((2 * nq) * 16 + ((g >> 1) << 3)) * 2;
                const uint32_t vd1 = vd0 + 32;
                ldm_x4_t(vH0, vd0);
                ldm_x4_t(vL0, vd0 + KTILE);
                ldm_x4_t(vH1, vd1);
                ldm_x4_t(vL1, vd1 + KTILE);
                float* o0 = O[4 * nq];
                float* o1 = O[4 * nq + 1];
                float* o2 = O[4 * nq + 2];
                float* o3 = O[4 * nq + 3];
                mma_bf16(o0, aPh, vH0);
                mma_bf16(o1, aPh, vH0 + 2);
                mma_bf16(o2, aPh, vH1);
                mma_bf16(o3, aPh, vH1 + 2);
                mma_bf16(o0, aPh, vL0);
                mma_bf16(o1, aPh, vL0 + 2);
                mma_bf16(o2, aPh, vL1);
                mma_bf16(o3, aPh, vL1 + 2);
                mma_bf16(o0, aPl, vH0);
                mma_bf16(o1, aPl, vH0 + 2);
                mma_bf16(o2, aPl, vH1);
                mma_bf16(o3, aPl, vH1 + 2);
            }
        }
        st = (st == 2) ? 0 : st + 1;
        sn = (sn == 2) ? 0 : sn + 1;
    }

    // ---- normalize + split-write O
    const float inv0 = 1.f / l0r, inv1 = 1.f / l1r;
    const size_t o0 = ((size_t)b * PS + row_g0) * PD + h * PHD;
    const size_t o1 = ((size_t)b * PS + row_g1) * PD + h * PHD;
    #pragma unroll
    for (int nt = 0; nt < 16; nt++) {
        const int col = nt * 8 + cq;
        uint32_t hh, ll;
        packhl(O[nt][0] * inv0, O[nt][1] * inv0, hh, ll);
        *(uint32_t*)&att_hi[o0 + col] = hh;
        *(uint32_t*)&att_lo[o0 + col] = ll;
        packhl(O[nt][2] * inv1, O[nt][3] * inv1, hh, ll);
        *(uint32_t*)&att_hi[o1 + col] = hh;
        *(uint32_t*)&att_lo[o1 + col] = ll;
    }
}

// ---------------------------------------------------------------------------
extern "C" void kernel_launch(void* const* d_in, const int* in_sizes, int n_in,
                              void* d_out, int out_size)
{
    const float* x     = (const float*)d_in[0];
    const float* w_qkv = (const float*)d_in[1];
    const float* b_qkv = (const float*)d_in[2];
    const float* w_out = (const float*)d_in[3];
    const float* b_out = (const float*)d_in[4];
    float* out = (float*)d_out;

    u16 *x_hi, *x_lo, *wq_hi, *wq_lo, *wo_hi, *wo_lo, *qk_hi, *qk_lo, *at_hi, *at_lo;
    cudaGetSymbolAddress((void**)&x_hi,  g_x_hi);
    cudaGetSymbolAddress((void**)&x_lo,  g_x_lo);
    cudaGetSymbolAddress((void**)&wq_hi, g_wqkv_hi);
    cudaGetSymbolAddress((void**)&wq_lo, g_wqkv_lo);
    cudaGetSymbolAddress((void**)&wo_hi, g_wout_hi);
    cudaGetSymbolAddress((void**)&wo_lo, g_wout_lo);
    cudaGetSymbolAddress((void**)&qk_hi, g_qkv_hi);
    cudaGetSymbolAddress((void**)&qk_lo, g_qkv_lo);
    cudaGetSymbolAddress((void**)&at_hi, g_att_hi);
    cudaGetSymbolAddress((void**)&at_lo, g_att_lo);

    cudaFuncSetAttribute(gemm_pre<true>,
                         cudaFuncAttributeMaxDynamicSharedMemorySize, GK2_SMEM);
    cudaFuncSetAttribute(gemm_pre<false>,
                         cudaFuncAttributeMaxDynamicSharedMemorySize, GK2_SMEM);
    cudaFuncSetAttribute(attn_mma,
                         cudaFuncAttributeMaxDynamicSharedMemorySize, AT_SMEM);

    // fused split of x, w_qkv, w_out (one launch)
    split_all<<<XB + WQB + WOB, 256>>>(x, x_hi, x_lo,
                                       w_qkv, wq_hi, wq_lo,
                                       w_out, wo_hi, wo_lo);

    gemm_pre<true><<<dim3(6144 / 128, 4096 / 128), 256, GK2_SMEM>>>(
        x_hi, x_lo, wq_hi, wq_lo, b_qkv, nullptr, qk_hi, qk_lo,
        PB * PS, 3 * PD, PD);
    attn_mma<<<dim3(PS / BQ, PB * PH), 256, AT_SMEM>>>(qk_hi, qk_lo, at_hi, at_lo);
    gemm_pre<false><<<dim3(2048 / 128, 4096 / 128), 256, GK2_SMEM>>>(
        at_hi, at_lo, wo_hi, wo_lo, b_out, out, nullptr, nullptr,
        PB * PS, PD, PD);
}

// round 15
// speedup vs baseline: 1.2692x; 1.2609x over previous
#include <cuda_runtime.h>
#include <cuda_bf16.h>
#include <cuda_fp16.h>
#include <cstdint>

#define PB 2
#define PS 2048
#define PD 2048
#define PH 16
#define PHD 128

typedef unsigned short u16;

// Scratch (device globals: allocation-free)
__device__ u16 g_x_hi[(size_t)PB * PS * PD];      // fp16
__device__ u16 g_x_lo[(size_t)PB * PS * PD];      // fp16
__device__ u16 g_wqkv_h[(size_t)PD * 3 * PD];     // fp16 (single)
__device__ u16 g_wout_h[(size_t)PD * PD];         // fp16 (single)
__device__ u16 g_qkv_hi[(size_t)PB * PS * 3 * PD];  // bf16 (attention input)
__device__ u16 g_qkv_lo[(size_t)PB * PS * 3 * PD];  // bf16
__device__ u16 g_att_hi[(size_t)PB * PS * PD];    // fp16 (out-proj A)
__device__ u16 g_att_lo[(size_t)PB * PS * PD];    // fp16

// ============================ helpers ======================================
__device__ __forceinline__ uint32_t smem_u32(const void* p) {
    uint32_t a;
    asm("{ .reg .u64 t; cvta.to.shared.u64 t, %1; cvt.u32.u64 %0, t; }"
        : "=r"(a) : "l"(p));
    return a;
}
__device__ __forceinline__ void ldm_x4(uint32_t* r, uint32_t addr) {
    asm volatile("ldmatrix.sync.aligned.m8n8.x4.shared.b16 {%0,%1,%2,%3}, [%4];"
                 : "=r"(r[0]), "=r"(r[1]), "=r"(r[2]), "=r"(r[3]) : "r"(addr));
}
__device__ __forceinline__ void ldm_x4_t(uint32_t* r, uint32_t addr) {
    asm volatile("ldmatrix.sync.aligned.m8n8.x4.trans.shared.b16 {%0,%1,%2,%3}, [%4];"
                 : "=r"(r[0]), "=r"(r[1]), "=r"(r[2]), "=r"(r[3]) : "r"(addr));
}
__device__ __forceinline__ void mma_bf16(float* d, const uint32_t* a, const uint32_t* b) {
    asm volatile(
        "mma.sync.aligned.m16n8k16.row.col.f32.bf16.bf16.f32 "
        "{%0,%1,%2,%3}, {%4,%5,%6,%7}, {%8,%9}, {%0,%1,%2,%3};"
        : "+f"(d[0]), "+f"(d[1]), "+f"(d[2]), "+f"(d[3])
        : "r"(a[0]), "r"(a[1]), "r"(a[2]), "r"(a[3]), "r"(b[0]), "r"(b[1]));
}
__device__ __forceinline__ void mma_f16(float* d, const uint32_t* a, const uint32_t* b) {
    asm volatile(
        "mma.sync.aligned.m16n8k16.row.col.f32.f16.f16.f32 "
        "{%0,%1,%2,%3}, {%4,%5,%6,%7}, {%8,%9}, {%0,%1,%2,%3};"
        : "+f"(d[0]), "+f"(d[1]), "+f"(d[2]), "+f"(d[3])
        : "r"(a[0]), "r"(a[1]), "r"(a[2]), "r"(a[3]), "r"(b[0]), "r"(b[1]));
}
__device__ __forceinline__ uint32_t pack2(__nv_bfloat16 x, __nv_bfloat16 y) {
    uint16_t xr = *reinterpret_cast<uint16_t*>(&x);
    uint16_t yr = *reinterpret_cast<uint16_t*>(&y);
    return (uint32_t)xr | ((uint32_t)yr << 16);
}
__device__ __forceinline__ uint32_t pack2h(__half x, __half y) {
    uint16_t xr = *reinterpret_cast<uint16_t*>(&x);
    uint16_t yr = *reinterpret_cast<uint16_t*>(&y);
    return (uint32_t)xr | ((uint32_t)yr << 16);
}
// bf16 hi/lo split (attention operands)
__device__ __forceinline__ void split4(float4 v, uint2& hi, uint2& lo) {
    __nv_bfloat16 h0 = __float2bfloat16(v.x), h1 = __float2bfloat16(v.y);
    __nv_bfloat16 h2 = __float2bfloat16(v.z), h3 = __float2bfloat16(v.w);
    float r0 = v.x - __bfloat162float(h0);
    float r1 = v.y - __bfloat162float(h1);
    float r2 = v.z - __bfloat162float(h2);
    float r3 = v.w - __bfloat162float(h3);
    hi = make_uint2(pack2(h0, h1), pack2(h2, h3));
    lo = make_uint2(pack2(__float2bfloat16(r0), __float2bfloat16(r1)),
                    pack2(__float2bfloat16(r2), __float2bfloat16(r3)));
}
// fp16 hi/lo split
__device__ __forceinline__ void split4h(float4 v, uint2& hi, uint2& lo) {
    __half h0 = __float2half_rn(v.x), h1 = __float2half_rn(v.y);
    __half h2 = __float2half_rn(v.z), h3 = __float2half_rn(v.w);
    float r0 = v.x - __half2float(h0);
    float r1 = v.y - __half2float(h1);
    float r2 = v.z - __half2float(h2);
    float r3 = v.w - __half2float(h3);
    hi = make_uint2(pack2h(h0, h1), pack2h(h2, h3));
    lo = make_uint2(pack2h(__float2half_rn(r0), __float2half_rn(r1)),
                    pack2h(__float2half_rn(r2), __float2half_rn(r3)));
}
__device__ __forceinline__ uint2 cvt4h(float4 v) {
    return make_uint2(pack2h(__float2half_rn(v.x), __float2half_rn(v.y)),
                      pack2h(__float2half_rn(v.z), __float2half_rn(v.w)));
}
__device__ __forceinline__ void packhl(float x, float y, uint32_t& hi, uint32_t& lo) {
    __nv_bfloat16 hx = __float2bfloat16(x), hy = __float2bfloat16(y);
    hi = pack2(hx, hy);
    lo = pack2(__float2bfloat16(x - __bfloat162float(hx)),
               __float2bfloat16(y - __bfloat162float(hy)));
}
__device__ __forceinline__ void packhl_h(float x, float y, uint32_t& hi, uint32_t& lo) {
    __half hx = __float2half_rn(x), hy = __float2half_rn(y);
    hi = pack2h(hx, hy);
    lo = pack2h(__float2half_rn(x - __half2float(hx)),
                __float2half_rn(y - __half2float(hy)));
}
__device__ __forceinline__ void cp16(uint32_t saddr, const void* gaddr) {
    asm volatile("cp.async.cg.shared.global [%0], [%1], 16;"
                 :: "r"(saddr), "l"(gaddr) : "memory");
}
#define CP_COMMIT() asm volatile("cp.async.commit_group;" ::: "memory")
#define CP_WAIT(n)  asm volatile("cp.async.wait_group %0;" :: "n"(n) : "memory")

// ============ fused input-format kernel (1 launch) ========================
// x -> fp16 hi/lo ; w_qkv -> fp16 ; w_out -> fp16
#define XB   ((PB * PS * PD) / 1024)          // 8192 blocks
#define WQB  ((PD * 3 * PD) / 1024)           // 12288 blocks
#define WOB  ((PD * PD) / 1024)               // 4096 blocks

__global__ void __launch_bounds__(256) split_all(
    const float* __restrict__ x,   u16* __restrict__ xh,  u16* __restrict__ xl,
    const float* __restrict__ wq,  u16* __restrict__ wqh,
    const float* __restrict__ wo,  u16* __restrict__ woh)
{
    int bid = blockIdx.x;
    if (bid < XB) {
        const size_t i = ((size_t)bid * 256 + threadIdx.x) * 4;
        float4 v = *(const float4*)(x + i);
        uint2 h, l;
        split4h(v, h, l);
        *(uint2*)&xh[i] = h;
        *(uint2*)&xl[i] = l;
    } else if (bid < XB + WQB) {
        const size_t i = ((size_t)(bid - XB) * 256 + threadIdx.x) * 4;
        *(uint2*)&wqh[i] = cvt4h(*(const float4*)(wq + i));
    } else {
        const size_t i = ((size_t)(bid - XB - WQB) * 256 + threadIdx.x) * 4;
        *(uint2*)&woh[i] = cvt4h(*(const float4*)(wo + i));
    }
}

// ====== fp16 2-term GEMM: C = (Ah+Al) @ Bh (+bias), 3-stage, 2 blk/SM =====
#define AROW2 80
#define BROW2 272
#define ATILE2 (128 * AROW2)                 // 10240 (one of Ah/Al)
#define BTILE2 (32 * BROW2)                  // 8704  (B hi only)
#define STAGE2 (2 * ATILE2 + BTILE2)         // 29184
#define GK2_SMEM (3 * STAGE2)                // 87552 -> 2 blocks/SM

template <bool SPLIT_OUT>
__global__ void __launch_bounds__(256, 2) gemm_pre(
    const u16* __restrict__ Ahi_g, const u16* __restrict__ Alo_g,
    const u16* __restrict__ Bh_g,
    const float* __restrict__ bias, float* __restrict__ C,
    u16* __restrict__ Chi, u16* __restrict__ Clo,
    int M, int N, int K)
{
    extern __shared__ char smc[];
    const uint32_t sb = smem_u32(smc);
    const int tid = threadIdx.x, lane = tid & 31, wid = tid >> 5;
    const int row0 = blockIdx.y * 128, col0 = blockIdx.x * 128;
    const int m0 = (wid & 3) * 32, n0 = (wid >> 2) * 64;
    const int g = lane >> 3, lr = lane & 7;

    float acc[2][8][4];
    #pragma unroll
    for (int i = 0; i < 2; i++)
        #pragma unroll
        for (int j = 0; j < 8; j++)
            #pragma unroll
            for (int q = 0; q < 4; q++) acc[i][j][q] = 0.f;

    auto LOADC = [&](int kc, int s) {
        const uint32_t sa = sb + (uint32_t)s * STAGE2;
        #pragma unroll
        for (int it = 0; it < 2; it++) {           // A: 512 chunks (hi+lo)
            int e = tid + it * 256;
            int r = e >> 2, c16 = e & 3;
            uint32_t off = sa + r * AROW2 + c16 * 16;
            size_t gi = (size_t)(row0 + r) * K + kc + c16 * 8;
            cp16(off, Ahi_g + gi);
            cp16(off + ATILE2, Alo_g + gi);
        }
        #pragma unroll
        for (int it = 0; it < 2; it++) {           // B: 512 chunks (hi only)
            int e = tid + it * 256;
            int k = e >> 4, c16 = e & 15;
            uint32_t off = sa + 2 * ATILE2 + k * BROW2 + c16 * 16;
            size_t gi = (size_t)(kc + k) * N + col0 + c16 * 8;
            cp16(off, Bh_g + gi);
        }
        CP_COMMIT();
    };

    auto MMAC = [&](int s) {
        const uint32_t Ah = sb + (uint32_t)s * STAGE2;
        const uint32_t Bh = Ah + 2 * ATILE2;
        #pragma unroll
        for (int ks = 0; ks < 2; ks++) {
            const int kb = ks * 16;
            uint32_t aH[2][4], aL[2][4];
            #pragma unroll
            for (int mt = 0; mt < 2; mt++) {
                uint32_t ad = Ah + (m0 + mt * 16 + lr + ((g & 1) << 3)) * AROW2
                                 + (kb + ((g >> 1) << 3)) * 2;
                ldm_x4(aH[mt], ad);
                ldm_x4(aL[mt], ad + ATILE2);
            }
            #pragma unroll
            for (int q = 0; q < 4; q++) {
                int kk = kb + lr + ((g & 1) << 3);
                uint32_t bd = Bh + kk * BROW2 + (n0 + q * 16 + ((g >> 1) << 3)) * 2;
                uint32_t tH[4];
                ldm_x4_t(tH, bd);
                #pragma unroll
                for (int mt = 0; mt < 2; mt++) {
                    mma_f16(acc[mt][2 * q],     aH[mt], tH);
                    mma_f16(acc[mt][2 * q + 1], aH[mt], tH + 2);
                    mma_f16(acc[mt][2 * q],     aL[mt], tH);
                    mma_f16(acc[mt][2 * q + 1], aL[mt], tH + 2);
                }
            }
        }
    };

    const int NCH = K >> 5;

    LOADC(0, 0);
    LOADC(32, 1);

    int s = 0;
    int sn = 2;
    for (int c = 0; c < NCH; c++) {
        if (c + 1 < NCH) { CP_WAIT(1); } else { CP_WAIT(0); }
        __syncthreads();
        if (c + 2 < NCH) LOADC((c + 2) << 5, sn);
        MMAC(s);
        s = (s == 2) ? 0 : s + 1;
        sn = (sn == 2) ? 0 : sn + 1;
    }

    #pragma unroll
    for (int mt = 0; mt < 2; mt++) {
        #pragma unroll
        for (int nt = 0; nt < 8; nt++) {
            const int r = row0 + m0 + mt * 16 + (lane >> 2);
            const int cc = col0 + n0 + nt * 8 + ((lane & 3) << 1);
            const float b0 = bias[cc], b1 = bias[cc + 1];
            float v00 = acc[mt][nt][0] + b0, v01 = acc[mt][nt][1] + b1;
            float v10 = acc[mt][nt][2] + b0, v11 = acc[mt][nt][3] + b1;
            if (SPLIT_OUT) {   // qkv: bf16 hi/lo for attention
                uint32_t h, l;
                packhl(v00, v01, h, l);
                *(uint32_t*)&Chi[(size_t)r * N + cc] = h;
                *(uint32_t*)&Clo[(size_t)r * N + cc] = l;
                packhl(v10, v11, h, l);
                *(uint32_t*)&Chi[(size_t)(r + 8) * N + cc] = h;
                *(uint32_t*)&Clo[(size_t)(r + 8) * N + cc] = l;
            } else {
                *(float2*)(C + (size_t)r * N + cc) = make_float2(v00, v01);
                *(float2*)(C + (size_t)(r + 8) * N + cc) = make_float2(v10, v11);
            }
        }
    }
}

// == Flash attention: bf16x3, Q-in-regs, 3-stage KV ring (R13 config) ======
// Epilogue now emits fp16 hi/lo (out-proj A operand).
#define BQ 128
#define BK 64
#define TROW 272
#define KTILE (64 * TROW)                  // 17408
#define KVSTG (4 * KTILE)                  // 69632
#define AT_SMEM (3 * KVSTG)                // 208896; stage2 doubles as Q landing

__global__ void __launch_bounds__(256, 1) attn_mma(
    const u16* __restrict__ qkv_hi, const u16* __restrict__ qkv_lo,
    u16* __restrict__ att_hi, u16* __restrict__ att_lo)
{
    extern __shared__ char smc[];
    const uint32_t sb = smem_u32(smc);
    const uint32_t sKV = sb;
    const uint32_t sQ  = sb + 2 * KVSTG;

    const int qt = (int)gridDim.x - 1 - (int)blockIdx.x;
    const int bh = blockIdx.y;
    const int b  = bh >> 4;
    const int h  = bh & 15;
    const int q0 = qt * BQ;
    const int tid  = threadIdx.x;
    const int lane = tid & 31;
    const int wid  = tid >> 5;
    const int lr   = lane & 7;
    const int g    = lane >> 3;
    const int rl   = lane >> 2;
    const int cq   = (lane & 3) << 1;

    const size_t rs = 3 * PD;
    const size_t base = (size_t)b * PS * rs + (size_t)h * PHD;
    const u16* qh = qkv_hi + base;
    const u16* ql = qkv_lo + base;
    const u16* kh = qh + PD;
    const u16* kl = ql + PD;
    const u16* vh = qh + 2 * PD;
    const u16* vl = ql + 2 * PD;

    auto load_kv = [&](int kt, int st) {
        const uint32_t sa = sKV + (uint32_t)st * KVSTG;
        const int k0 = kt * BK;
        #pragma unroll
        for (int it = 0; it < 4; it++) {
            int e = tid + it * 256;
            int r = e >> 4, c16 = e & 15;
            uint32_t koff = sa + r * TROW + c16 * 16;
            uint32_t voff = koff + 2 * KTILE;
            size_t gi = (size_t)(k0 + r) * rs + c16 * 8;
            cp16(koff, kh + gi);
            cp16(koff + KTILE, kl + gi);
            cp16(voff, vh + gi);
            cp16(voff + KTILE, vl + gi);
        }
        CP_COMMIT();
    };

    // Q (hi at sQ, lo at sQ + 2*KTILE)
    #pragma unroll
    for (int it = 0; it < 8; it++) {
        int e = tid + it * 256;
        int r = e >> 4, c16 = e & 15;
        uint32_t off = sQ + r * TROW + c16 * 16;
        size_t gi = (size_t)(q0 + r) * rs + c16 * 8;
        cp16(off, qh + gi);
        cp16(off + 2 * KTILE, ql + gi);
    }
    CP_COMMIT();

    const int nkt = 2 * qt + 2;
    load_kv(0, 0);
    if (nkt > 1) load_kv(1, 1);

    CP_WAIT(2);
    __syncthreads();
    uint32_t qH[8][4], qL[8][4];
    #pragma unroll
    for (int ks = 0; ks < 8; ks++) {
        const uint32_t ad = sQ + (wid * 16 + lr + ((g & 1) << 3)) * TROW
                               + (ks * 16 + ((g >> 1) << 3)) * 2;
        ldm_x4(qH[ks], ad);
        ldm_x4(qL[ks], ad + 2 * KTILE);
    }
    __syncthreads();

    float O[16][4];
    #pragma unroll
    for (int nt = 0; nt < 16; nt++)
        #pragma unroll
        for (int c = 0; c < 4; c++) O[nt][c] = 0.f;
    float m0r = -1e30f, m1r = -1e30f, l0r = 0.f, l1r = 0.f;
    const float scale = 0.08838834764831845f;
    const int row_g0 = q0 + wid * 16 + rl;
    const int row_g1 = row_g0 + 8;

    int st = 0;
    int sn = 2;
    for (int kt = 0; kt < nkt; kt++) {
        const int k0 = kt * BK;
        if (kt + 1 < nkt) { CP_WAIT(1); } else { CP_WAIT(0); }
        __syncthreads();
        if (kt + 2 < nkt) load_kv(kt + 2, sn);

        const uint32_t sKhi = sKV + (uint32_t)st * KVSTG;
        const uint32_t sVhi = sKhi + 2 * KTILE;

        float S[8][4];
        #pragma unroll
        for (int j = 0; j < 8; j++)
            #pragma unroll
            for (int c = 0; c < 4; c++) S[j][c] = 0.f;

        #pragma unroll
        for (int ks = 0; ks < 8; ks++) {
            #pragma unroll
            for (int p = 0; p < 4; p++) {
                uint32_t kH[4], kL[4];
                const uint32_t kd = sKhi + (p * 16 + lr + ((g >> 1) << 3)) * TROW
                                         + (ks * 16 + ((g & 1) << 3)) * 2;
                ldm_x4(kH, kd);
                ldm_x4(kL, kd + KTILE);
                mma_bf16(S[2 * p],     qH[ks], kH);
                mma_bf16(S[2 * p + 1], qH[ks], kH + 2);
                mma_bf16(S[2 * p],     qH[ks], kL);
                mma_bf16(S[2 * p + 1], qH[ks], kL + 2);
                mma_bf16(S[2 * p],     qL[ks], kH);
                mma_bf16(S[2 * p + 1], qL[ks], kH + 2);
            }
        }

        const bool need_mask = (k0 + BK - 1 > q0);
        float mx0 = -1e30f, mx1 = -1e30f;
        #pragma unroll
        for (int j = 0; j < 8; j++) {
            #pragma unroll
            for (int c = 0; c < 4; c++) {
                float s = S[j][c] * scale;
                if (need_mask) {
                    const int col = k0 + j * 8 + cq + (c & 1);
                    const int row = (c < 2) ? row_g0 : row_g1;
                    if (col > row) s = -1e30f;
                }
                S[j][c] = s;
            }
            mx0 = fmaxf(mx0, fmaxf(S[j][0], S[j][1]));
            mx1 = fmaxf(mx1, fmaxf(S[j][2], S[j][3]));
        }
        #pragma unroll
        for (int off = 1; off <= 2; off <<= 1) {
            mx0 = fmaxf(mx0, __shfl_xor_sync(0xffffffffu, mx0, off));
            mx1 = fmaxf(mx1, __shfl_xor_sync(0xffffffffu, mx1, off));
        }
        const float nm0 = fmaxf(m0r, mx0), nm1 = fmaxf(m1r, mx1);
        const float al0 = __expf(m0r - nm0), al1 = __expf(m1r - nm1);
        float sum0 = 0.f, sum1 = 0.f;
        #pragma unroll
        for (int j = 0; j < 8; j++) {
            S[j][0] = __expf(S[j][0] - nm0);
            S[j][1] = __expf(S[j][1] - nm0);
            S[j][2] = __expf(S[j][2] - nm1);
            S[j][3] = __expf(S[j][3] - nm1);
            sum0 += S[j][0] + S[j][1];
            sum1 += S[j][2] + S[j][3];
        }
        #pragma unroll
        for (int off = 1; off <= 2; off <<= 1) {
            sum0 += __shfl_xor_sync(0xffffffffu, sum0, off);
            sum1 += __shfl_xor_sync(0xffffffffu, sum1, off);
        }
        l0r = l0r * al0 + sum0;
        l1r = l1r * al1 + sum1;
        m0r = nm0; m1r = nm1;
        #pragma unroll
        for (int nt = 0; nt < 16; nt++) {
            O[nt][0] *= al0; O[nt][1] *= al0;
            O[nt][2] *= al1; O[nt][3] *= al1;
        }

        #pragma unroll
        for (int kk = 0; kk < 4; kk++) {
            uint32_t aPh[4], aPl[4];
            const int j0 = 2 * kk, j1 = 2 * kk + 1;
            packhl(S[j0][0], S[j0][1], aPh[0], aPl[0]);
            packhl(S[j0][2], S[j0][3], aPh[1], aPl[1]);
            packhl(S[j1][0], S[j1][1], aPh[2], aPl[2]);
            packhl(S[j1][2], S[j1][3], aPh[3], aPl[3]);
            #pragma unroll
            for (int nq = 0; nq < 4; nq++) {
                uint32_t vH0[4], vL0[4], vH1[4], vL1[4];
                const uint32_t vd0 = sVhi + (kk * 16 + lr + ((g & 1) << 3)) * TROW
                                          + ((2 * nq) * 16 + ((g >> 1) << 3)) * 2;
                const uint32_t vd1 = vd0 + 32;
                ldm_x4_t(vH0, vd0);
                ldm_x4_t(vL0, vd0 + KTILE);
                ldm_x4_t(vH1, vd1);
                ldm_x4_t(vL1, vd1 + KTILE);
                float* o0 = O[4 * nq];
                float* o1 = O[4 * nq + 1];
                float* o2 = O[4 * nq + 2];
                float* o3 = O[4 * nq + 3];
                mma_bf16(o0, aPh, vH0);
                mma_bf16(o1, aPh, vH0 + 2);
                mma_bf16(o2, aPh, vH1);
                mma_bf16(o3, aPh, vH1 + 2);
                mma_bf16(o0, aPh, vL0);
                mma_bf16(o1, aPh, vL0 + 2);
                mma_bf16(o2, aPh, vL1);
                mma_bf16(o3, aPh, vL1 + 2);
                mma_bf16(o0, aPl, vH0);
                mma_bf16(o1, aPl, vH0 + 2);
                mma_bf16(o2, aPl, vH1);
                mma_bf16(o3, aPl, vH1 + 2);
            }
        }
        st = (st == 2) ? 0 : st + 1;
        sn = (sn == 2) ? 0 : sn + 1;
    }

    // ---- normalize + fp16 hi/lo split-write (out-proj A operand)
    const float inv0 = 1.f / l0r, inv1 = 1.f / l1r;
    const size_t o0 = ((size_t)b * PS + row_g0) * PD + h * PHD;
    const size_t o1 = ((size_t)b * PS + row_g1) * PD + h * PHD;
    #pragma unroll
    for (int nt = 0; nt < 16; nt++) {
        const int col = nt * 8 + cq;
        uint32_t hh, ll;
        packhl_h(O[nt][0] * inv0, O[nt][1] * inv0, hh, ll);
        *(uint32_t*)&att_hi[o0 + col] = hh;
        *(uint32_t*)&att_lo[o0 + col] = ll;
        packhl_h(O[nt][2] * inv1, O[nt][3] * inv1, hh, ll);
        *(uint32_t*)&att_hi[o1 + col] = hh;
        *(uint32_t*)&att_lo[o1 + col] = ll;
    }
}

// ---------------------------------------------------------------------------
extern "C" void kernel_launch(void* const* d_in, const int* in_sizes, int n_in,
                              void* d_out, int out_size)
{
    const float* x     = (const float*)d_in[0];
    const float* w_qkv = (const float*)d_in[1];
    const float* b_qkv = (const float*)d_in[2];
    const float* w_out = (const float*)d_in[3];
    const float* b_out = (const float*)d_in[4];
    float* out = (float*)d_out;

    u16 *x_hi, *x_lo, *wq_h, *wo_h, *qk_hi, *qk_lo, *at_hi, *at_lo;
    cudaGetSymbolAddress((void**)&x_hi,  g_x_hi);
    cudaGetSymbolAddress((void**)&x_lo,  g_x_lo);
    cudaGetSymbolAddress((void**)&wq_h,  g_wqkv_h);
    cudaGetSymbolAddress((void**)&wo_h,  g_wout_h);
    cudaGetSymbolAddress((void**)&qk_hi, g_qkv_hi);
    cudaGetSymbolAddress((void**)&qk_lo, g_qkv_lo);
    cudaGetSymbolAddress((void**)&at_hi, g_att_hi);
    cudaGetSymbolAddress((void**)&at_lo, g_att_lo);

    cudaFuncSetAttribute(gemm_pre<true>,
                         cudaFuncAttributeMaxDynamicSharedMemorySize, GK2_SMEM);
    cudaFuncSetAttribute(gemm_pre<false>,
                         cudaFuncAttributeMaxDynamicSharedMemorySize, GK2_SMEM);
    cudaFuncSetAttribute(attn_mma,
                         cudaFuncAttributeMaxDynamicSharedMemorySize, AT_SMEM);

    split_all<<<XB + WQB + WOB, 256>>>(x, x_hi, x_lo, w_qkv, wq_h, w_out, wo_h);

    // QKV projection (fp16 2-term) -> bf16 hi/lo qkv
    gemm_pre<true><<<dim3(6144 / 128, 4096 / 128), 256, GK2_SMEM>>>(
        x_hi, x_lo, wq_h, b_qkv, nullptr, qk_hi, qk_lo,
        PB * PS, 3 * PD, PD);
    // Causal attention (bf16 3-term, unchanged) -> fp16 hi/lo att
    attn_mma<<<dim3(PS / BQ, PB * PH), 256, AT_SMEM>>>(qk_hi, qk_lo, at_hi, at_lo);
    // Output projection (fp16 2-term) -> fp32 out
    gemm_pre<false><<<dim3(2048 / 128, 4096 / 128), 256, GK2_SMEM>>>(
        at_hi, at_lo, wo_h, b_out, out, nullptr, nullptr,
        PB * PS, PD, PD);
}

// round 16
// speedup vs baseline: 1.4064x; 1.1081x over previous
#include <cuda_runtime.h>
#include <cuda_bf16.h>
#include <cuda_fp16.h>
#include <cstdint>

#define PB 2
#define PS 2048
#define PD 2048
#define PH 16
#define PHD 128

typedef unsigned short u16;

// Scratch (device globals: allocation-free)
__device__ u16 g_x_hi[(size_t)PB * PS * PD];      // fp16
__device__ u16 g_x_lo[(size_t)PB * PS * PD];      // fp16
__device__ u16 g_wqkv_h[(size_t)PD * 3 * PD];     // fp16 (single)
__device__ u16 g_wout_h[(size_t)PD * PD];         // fp16 (single)
__device__ u16 g_qkv_hi[(size_t)PB * PS * 3 * PD];  // Q: fp16 hi; K,V: fp16 single
__device__ u16 g_qkv_lo[(size_t)PB * PS * 3 * PD];  // Q: fp16 lo (K,V unused)
__device__ u16 g_att_hi[(size_t)PB * PS * PD];    // fp16 (out-proj A hi)
__device__ u16 g_att_lo[(size_t)PB * PS * PD];    // fp16 (out-proj A lo)

// ============================ helpers ======================================
__device__ __forceinline__ uint32_t smem_u32(const void* p) {
    uint32_t a;
    asm("{ .reg .u64 t; cvta.to.shared.u64 t, %1; cvt.u32.u64 %0, t; }"
        : "=r"(a) : "l"(p));
    return a;
}
__device__ __forceinline__ void ldm_x4(uint32_t* r, uint32_t addr) {
    asm volatile("ldmatrix.sync.aligned.m8n8.x4.shared.b16 {%0,%1,%2,%3}, [%4];"
                 : "=r"(r[0]), "=r"(r[1]), "=r"(r[2]), "=r"(r[3]) : "r"(addr));
}
__device__ __forceinline__ void ldm_x4_t(uint32_t* r, uint32_t addr) {
    asm volatile("ldmatrix.sync.aligned.m8n8.x4.trans.shared.b16 {%0,%1,%2,%3}, [%4];"
                 : "=r"(r[0]), "=r"(r[1]), "=r"(r[2]), "=r"(r[3]) : "r"(addr));
}
__device__ __forceinline__ void mma_f16(float* d, const uint32_t* a, const uint32_t* b) {
    asm volatile(
        "mma.sync.aligned.m16n8k16.row.col.f32.f16.f16.f32 "
        "{%0,%1,%2,%3}, {%4,%5,%6,%7}, {%8,%9}, {%0,%1,%2,%3};"
        : "+f"(d[0]), "+f"(d[1]), "+f"(d[2]), "+f"(d[3])
        : "r"(a[0]), "r"(a[1]), "r"(a[2]), "r"(a[3]), "r"(b[0]), "r"(b[1]));
}
__device__ __forceinline__ uint32_t pack2h(__half x, __half y) {
    uint16_t xr = *reinterpret_cast<uint16_t*>(&x);
    uint16_t yr = *reinterpret_cast<uint16_t*>(&y);
    return (uint32_t)xr | ((uint32_t)yr << 16);
}
__device__ __forceinline__ void split4h(float4 v, uint2& hi, uint2& lo) {
    __half h0 = __float2half_rn(v.x), h1 = __float2half_rn(v.y);
    __half h2 = __float2half_rn(v.z), h3 = __float2half_rn(v.w);
    float r0 = v.x - __half2float(h0);
    float r1 = v.y - __half2float(h1);
    float r2 = v.z - __half2float(h2);
    float r3 = v.w - __half2float(h3);
    hi = make_uint2(pack2h(h0, h1), pack2h(h2, h3));
    lo = make_uint2(pack2h(__float2half_rn(r0), __float2half_rn(r1)),
                    pack2h(__float2half_rn(r2), __float2half_rn(r3)));
}
__device__ __forceinline__ uint2 cvt4h(float4 v) {
    return make_uint2(pack2h(__float2half_rn(v.x), __float2half_rn(v.y)),
                      pack2h(__float2half_rn(v.z), __float2half_rn(v.w)));
}
__device__ __forceinline__ void packhl_h(float x, float y, uint32_t& hi, uint32_t& lo) {
    __half hx = __float2half_rn(x), hy = __float2half_rn(y);
    hi = pack2h(hx, hy);
    lo = pack2h(__float2half_rn(x - __half2float(hx)),
                __float2half_rn(y - __half2float(hy)));
}
__device__ __forceinline__ void cp16(uint32_t saddr, const void* gaddr) {
    asm volatile("cp.async.cg.shared.global [%0], [%1], 16;"
                 :: "r"(saddr), "l"(gaddr) : "memory");
}
#define CP_COMMIT() asm volatile("cp.async.commit_group;" ::: "memory")
#define CP_WAIT(n)  asm volatile("cp.async.wait_group %0;" :: "n"(n) : "memory")

// ============ fused input-format kernel (1 launch) ========================
#define XB   ((PB * PS * PD) / 1024)
#define WQB  ((PD * 3 * PD) / 1024)
#define WOB  ((PD * PD) / 1024)

__global__ void __launch_bounds__(256) split_all(
    const float* __restrict__ x,   u16* __restrict__ xh,  u16* __restrict__ xl,
    const float* __restrict__ wq,  u16* __restrict__ wqh,
    const float* __restrict__ wo,  u16* __restrict__ woh)
{
    int bid = blockIdx.x;
    if (bid < XB) {
        const size_t i = ((size_t)bid * 256 + threadIdx.x) * 4;
        float4 v = *(const float4*)(x + i);
        uint2 h, l;
        split4h(v, h, l);
        *(uint2*)&xh[i] = h;
        *(uint2*)&xl[i] = l;
    } else if (bid < XB + WQB) {
        const size_t i = ((size_t)(bid - XB) * 256 + threadIdx.x) * 4;
        *(uint2*)&wqh[i] = cvt4h(*(const float4*)(wq + i));
    } else {
        const size_t i = ((size_t)(bid - XB - WQB) * 256 + threadIdx.x) * 4;
        *(uint2*)&woh[i] = cvt4h(*(const float4*)(wo + i));
    }
}

// ====== fp16 2-term GEMM: C = (Ah+Al) @ Bh (+bias), 3-stage, 2 blk/SM =====
// SPLIT_OUT: per-column-type epilogue for qkv (Q fp16 hi/lo; K,V fp16 single)
#define AROW2 80
#define BROW2 272
#define ATILE2 (128 * AROW2)
#define BTILE2 (32 * BROW2)
#define STAGE2 (2 * ATILE2 + BTILE2)         // 29184
#define GK2_SMEM (3 * STAGE2)                // 87552

template <bool SPLIT_OUT>
__global__ void __launch_bounds__(256, 2) gemm_pre(
    const u16* __restrict__ Ahi_g, const u16* __restrict__ Alo_g,
    const u16* __restrict__ Bh_g,
    const float* __restrict__ bias, float* __restrict__ C,
    u16* __restrict__ Chi, u16* __restrict__ Clo,
    int M, int N, int K)
{
    extern __shared__ char smc[];
    const uint32_t sb = smem_u32(smc);
    const int tid = threadIdx.x, lane = tid & 31, wid = tid >> 5;
    const int row0 = blockIdx.y * 128, col0 = blockIdx.x * 128;
    const int m0 = (wid & 3) * 32, n0 = (wid >> 2) * 64;
    const int g = lane >> 3, lr = lane & 7;

    float acc[2][8][4];
    #pragma unroll
    for (int i = 0; i < 2; i++)
        #pragma unroll
        for (int j = 0; j < 8; j++)
            #pragma unroll
            for (int q = 0; q < 4; q++) acc[i][j][q] = 0.f;

    auto LOADC = [&](int kc, int s) {
        const uint32_t sa = sb + (uint32_t)s * STAGE2;
        #pragma unroll
        for (int it = 0; it < 2; it++) {
            int e = tid + it * 256;
            int r = e >> 2, c16 = e & 3;
            uint32_t off = sa + r * AROW2 + c16 * 16;
            size_t gi = (size_t)(row0 + r) * K + kc + c16 * 8;
            cp16(off, Ahi_g + gi);
            cp16(off + ATILE2, Alo_g + gi);
        }
        #pragma unroll
        for (int it = 0; it < 2; it++) {
            int e = tid + it * 256;
            int k = e >> 4, c16 = e & 15;
            uint32_t off = sa + 2 * ATILE2 + k * BROW2 + c16 * 16;
            size_t gi = (size_t)(kc + k) * N + col0 + c16 * 8;
            cp16(off, Bh_g + gi);
        }
        CP_COMMIT();
    };

    auto MMAC = [&](int s) {
        const uint32_t Ah = sb + (uint32_t)s * STAGE2;
        const uint32_t Bh = Ah + 2 * ATILE2;
        #pragma unroll
        for (int ks = 0; ks < 2; ks++) {
            const int kb = ks * 16;
            uint32_t aH[2][4], aL[2][4];
            #pragma unroll
            for (int mt = 0; mt < 2; mt++) {
                uint32_t ad = Ah + (m0 + mt * 16 + lr + ((g & 1) << 3)) * AROW2
                                 + (kb + ((g >> 1) << 3)) * 2;
                ldm_x4(aH[mt], ad);
                ldm_x4(aL[mt], ad + ATILE2);
            }
            #pragma unroll
            for (int q = 0; q < 4; q++) {
                int kk = kb + lr + ((g & 1) << 3);
                uint32_t bd = Bh + kk * BROW2 + (n0 + q * 16 + ((g >> 1) << 3)) * 2;
                uint32_t tH[4];
                ldm_x4_t(tH, bd);
                #pragma unroll
                for (int mt = 0; mt < 2; mt++) {
                    mma_f16(acc[mt][2 * q],     aH[mt], tH);
                    mma_f16(acc[mt][2 * q + 1], aH[mt], tH + 2);
                    mma_f16(acc[mt][2 * q],     aL[mt], tH);
                    mma_f16(acc[mt][2 * q + 1], aL[mt], tH + 2);
                }
            }
        }
    };

    const int NCH = K >> 5;

    LOADC(0, 0);
    LOADC(32, 1);

    int s = 0;
    int sn = 2;
    for (int c = 0; c < NCH; c++) {
        if (c + 1 < NCH) { CP_WAIT(1); } else { CP_WAIT(0); }
        __syncthreads();
        if (c + 2 < NCH) LOADC((c + 2) << 5, sn);
        MMAC(s);
        s = (s == 2) ? 0 : s + 1;
        sn = (sn == 2) ? 0 : sn + 1;
    }

    // epilogue
    const bool q_region = SPLIT_OUT && (col0 < PD);   // Q cols: fp16 hi/lo
    #pragma unroll
    for (int mt = 0; mt < 2; mt++) {
        #pragma unroll
        for (int nt = 0; nt < 8; nt++) {
            const int r = row0 + m0 + mt * 16 + (lane >> 2);
            const int cc = col0 + n0 + nt * 8 + ((lane & 3) << 1);
            const float b0 = bias[cc], b1 = bias[cc + 1];
            float v00 = acc[mt][nt][0] + b0, v01 = acc[mt][nt][1] + b1;
            float v10 = acc[mt][nt][2] + b0, v11 = acc[mt][nt][3] + b1;
            if (SPLIT_OUT) {
                if (q_region) {
                    uint32_t h, l;
                    packhl_h(v00, v01, h, l);
                    *(uint32_t*)&Chi[(size_t)r * N + cc] = h;
                    *(uint32_t*)&Clo[(size_t)r * N + cc] = l;
                    packhl_h(v10, v11, h, l);
                    *(uint32_t*)&Chi[(size_t)(r + 8) * N + cc] = h;
                    *(uint32_t*)&Clo[(size_t)(r + 8) * N + cc] = l;
                } else {   // K or V: single fp16
                    *(uint32_t*)&Chi[(size_t)r * N + cc] =
                        pack2h(__float2half_rn(v00), __float2half_rn(v01));
                    *(uint32_t*)&Chi[(size_t)(r + 8) * N + cc] =
                        pack2h(__float2half_rn(v10), __float2half_rn(v11));
                }
            } else {
                *(float2*)(C + (size_t)r * N + cc) = make_float2(v00, v01);
                *(float2*)(C + (size_t)(r + 8) * N + cc) = make_float2(v10, v11);
            }
        }
    }
}

// ==== Flash attention: all-fp16 asymmetric (K,V single; Q,P hi/lo) ========
// Q in registers; 3-stage KV ring; Q lands overlapping stages 1-2.
#define BQ 128
#define BK 64
#define TROW 272
#define KTILE (64 * TROW)                  // 17408
#define KVSTG (2 * KTILE)                  // 34816: K, V (single each)
#define QBYTES (128 * TROW)                // 34816 per Q half
#define AT_SMEM (3 * KVSTG)                // 104448

__global__ void __launch_bounds__(256, 1) attn_mma(
    const u16* __restrict__ qkv_hi, const u16* __restrict__ qkv_lo,
    u16* __restrict__ att_hi, u16* __restrict__ att_lo)
{
    extern __shared__ char smc[];
    const uint32_t sb = smem_u32(smc);
    const uint32_t sKV = sb;
    const uint32_t sQ  = sb + KVSTG;           // Q hi = stage1, Q lo = stage2

    const int qt = (int)gridDim.x - 1 - (int)blockIdx.x;
    const int bh = blockIdx.y;
    const int b  = bh >> 4;
    const int h  = bh & 15;
    const int q0 = qt * BQ;
    const int tid  = threadIdx.x;
    const int lane = tid & 31;
    const int wid  = tid >> 5;
    const int lr   = lane & 7;
    const int g    = lane >> 3;
    const int rl   = lane >> 2;
    const int cq   = (lane & 3) << 1;

    const size_t rs = 3 * PD;
    const size_t base = (size_t)b * PS * rs + (size_t)h * PHD;
    const u16* qh = qkv_hi + base;
    const u16* ql = qkv_lo + base;
    const u16* kh = qh + PD;          // K single fp16
    const u16* vh = qh + 2 * PD;      // V single fp16

    auto load_kv = [&](int kt, int st) {
        const uint32_t sa = sKV + (uint32_t)st * KVSTG;
        const int k0 = kt * BK;
        #pragma unroll
        for (int it = 0; it < 4; it++) {
            int e = tid + it * 256;
            int r = e >> 4, c16 = e & 15;
            uint32_t koff = sa + r * TROW + c16 * 16;
            size_t gi = (size_t)(k0 + r) * rs + c16 * 8;
            cp16(koff, kh + gi);
            cp16(koff + KTILE, vh + gi);
        }
        CP_COMMIT();
    };

    // Q (hi at sQ, lo at sQ + QBYTES)
    #pragma unroll
    for (int it = 0; it < 8; it++) {
        int e = tid + it * 256;
        int r = e >> 4, c16 = e & 15;
        uint32_t off = sQ + r * TROW + c16 * 16;
        size_t gi = (size_t)(q0 + r) * rs + c16 * 8;
        cp16(off, qh + gi);
        cp16(off + QBYTES, ql + gi);
    }
    CP_COMMIT();

    const int nkt = 2 * qt + 2;
    load_kv(0, 0);

    // Q fragments -> registers (fp16), then stages 1/2 become KV stages
    CP_WAIT(1);          // Q landed (kv0 in flight)
    __syncthreads();
    uint32_t qH[8][4], qL[8][4];
    #pragma unroll
    for (int ks = 0; ks < 8; ks++) {
        const uint32_t ad = sQ + (wid * 16 + lr + ((g & 1) << 3)) * TROW
                               + (ks * 16 + ((g >> 1) << 3)) * 2;
        ldm_x4(qH[ks], ad);
        ldm_x4(qL[ks], ad + QBYTES);
    }
    __syncthreads();     // all warps extracted Q
    if (nkt > 1) load_kv(1, 1);

    float O[16][4];
    #pragma unroll
    for (int nt = 0; nt < 16; nt++)
        #pragma unroll
        for (int c = 0; c < 4; c++) O[nt][c] = 0.f;
    float m0r = -1e30f, m1r = -1e30f, l0r = 0.f, l1r = 0.f;
    const float scale = 0.08838834764831845f;
    const int row_g0 = q0 + wid * 16 + rl;
    const int row_g1 = row_g0 + 8;

    int st = 0;
    int sn = 2;
    for (int kt = 0; kt < nkt; kt++) {
        const int k0 = kt * BK;
        if (kt + 1 < nkt) { CP_WAIT(1); } else { CP_WAIT(0); }
        __syncthreads();
        if (kt + 2 < nkt) load_kv(kt + 2, sn);

        const uint32_t sKt = sKV + (uint32_t)st * KVSTG;
        const uint32_t sVt = sKt + KTILE;

        // ---- S = Q K^T : (Qh + Ql) x K, fp16, 2 terms
        float S[8][4];
        #pragma unroll
        for (int j = 0; j < 8; j++)
            #pragma unroll
            for (int c = 0; c < 4; c++) S[j][c] = 0.f;

        #pragma unroll
        for (int ks = 0; ks < 8; ks++) {
            #pragma unroll
            for (int p = 0; p < 4; p++) {
                uint32_t kH[4];
                const uint32_t kd = sKt + (p * 16 + lr + ((g >> 1) << 3)) * TROW
                                        + (ks * 16 + ((g & 1) << 3)) * 2;
                ldm_x4(kH, kd);
                mma_f16(S[2 * p],     qH[ks], kH);
                mma_f16(S[2 * p + 1], qH[ks], kH + 2);
                mma_f16(S[2 * p],     qL[ks], kH);
                mma_f16(S[2 * p + 1], qL[ks], kH + 2);
            }
        }

        // ---- scale + mask + online softmax
        const bool need_mask = (k0 + BK - 1 > q0);
        float mx0 = -1e30f, mx1 = -1e30f;
        #pragma unroll
        for (int j = 0; j < 8; j++) {
            #pragma unroll
            for (int c = 0; c < 4; c++) {
                float s = S[j][c] * scale;
                if (need_mask) {
                    const int col = k0 + j * 8 + cq + (c & 1);
                    const int row = (c < 2) ? row_g0 : row_g1;
                    if (col > row) s = -1e30f;
                }
                S[j][c] = s;
            }
            mx0 = fmaxf(mx0, fmaxf(S[j][0], S[j][1]));
            mx1 = fmaxf(mx1, fmaxf(S[j][2], S[j][3]));
        }
        #pragma unroll
        for (int off = 1; off <= 2; off <<= 1) {
            mx0 = fmaxf(mx0, __shfl_xor_sync(0xffffffffu, mx0, off));
            mx1 = fmaxf(mx1, __shfl_xor_sync(0xffffffffu, mx1, off));
        }
        const float nm0 = fmaxf(m0r, mx0), nm1 = fmaxf(m1r, mx1);
        const float al0 = __expf(m0r - nm0), al1 = __expf(m1r - nm1);
        float sum0 = 0.f, sum1 = 0.f;
        #pragma unroll
        for (int j = 0; j < 8; j++) {
            S[j][0] = __expf(S[j][0] - nm0);
            S[j][1] = __expf(S[j][1] - nm0);
            S[j][2] = __expf(S[j][2] - nm1);
            S[j][3] = __expf(S[j][3] - nm1);
            sum0 += S[j][0] + S[j][1];
            sum1 += S[j][2] + S[j][3];
        }
        #pragma unroll
        for (int off = 1; off <= 2; off <<= 1) {
            sum0 += __shfl_xor_sync(0xffffffffu, sum0, off);
            sum1 += __shfl_xor_sync(0xffffffffu, sum1, off);
        }
        l0r = l0r * al0 + sum0;
        l1r = l1r * al1 + sum1;
        m0r = nm0; m1r = nm1;
        #pragma unroll
        for (int nt = 0; nt < 16; nt++) {
            O[nt][0] *= al0; O[nt][1] *= al0;
            O[nt][2] *= al1; O[nt][3] *= al1;
        }

        // ---- O += P V : (Ph + Pl) x V, fp16, 2 terms
        #pragma unroll
        for (int kk = 0; kk < 4; kk++) {
            uint32_t aPh[4], aPl[4];
            const int j0 = 2 * kk, j1 = 2 * kk + 1;
            packhl_h(S[j0][0], S[j0][1], aPh[0], aPl[0]);
            packhl_h(S[j0][2], S[j0][3], aPh[1], aPl[1]);
            packhl_h(S[j1][0], S[j1][1], aPh[2], aPl[2]);
            packhl_h(S[j1][2], S[j1][3], aPh[3], aPl[3]);
            #pragma unroll
            for (int nq = 0; nq < 4; nq++) {
                uint32_t vH0[4], vH1[4];
                const uint32_t vd0 = sVt + (kk * 16 + lr + ((g & 1) << 3)) * TROW
                                         + ((2 * nq) * 16 + ((g >> 1) << 3)) * 2;
                ldm_x4_t(vH0, vd0);
                ldm_x4_t(vH1, vd0 + 32);
                float* o0 = O[4 * nq];
                float* o1 = O[4 * nq + 1];
                float* o2 = O[4 * nq + 2];
                float* o3 = O[4 * nq + 3];
                mma_f16(o0, aPh, vH0);
                mma_f16(o1, aPh, vH0 + 2);
                mma_f16(o2, aPh, vH1);
                mma_f16(o3, aPh, vH1 + 2);
                mma_f16(o0, aPl, vH0);
                mma_f16(o1, aPl, vH0 + 2);
                mma_f16(o2, aPl, vH1);
                mma_f16(o3, aPl, vH1 + 2);
            }
        }
        st = (st == 2) ? 0 : st + 1;
        sn = (sn == 2) ? 0 : sn + 1;
    }

    // ---- normalize + fp16 hi/lo split-write (out-proj A operand)
    const float inv0 = 1.f / l0r, inv1 = 1.f / l1r;
    const size_t o0 = ((size_t)b * PS + row_g0) * PD + h * PHD;
    const size_t o1 = ((size_t)b * PS + row_g1) * PD + h * PHD;
    #pragma unroll
    for (int nt = 0; nt < 16; nt++) {
        const int col = nt * 8 + cq;
        uint32_t hh, ll;
        packhl_h(O[nt][0] * inv0, O[nt][1] * inv0, hh, ll);
        *(uint32_t*)&att_hi[o0 + col] = hh;
        *(uint32_t*)&att_lo[o0 + col] = ll;
        packhl_h(O[nt][2] * inv1, O[nt][3] * inv1, hh, ll);
        *(uint32_t*)&att_hi[o1 + col] = hh;
        *(uint32_t*)&att_lo[o1 + col] = ll;
    }
}

// ---------------------------------------------------------------------------
extern "C" void kernel_launch(void* const* d_in, const int* in_sizes, int n_in,
                              void* d_out, int out_size)
{
    const float* x     = (const float*)d_in[0];
    const float* w_qkv = (const float*)d_in[1];
    const float* b_qkv = (const float*)d_in[2];
    const float* w_out = (const float*)d_in[3];
    const float* b_out = (const float*)d_in[4];
    float* out = (float*)d_out;

    u16 *x_hi, *x_lo, *wq_h, *wo_h, *qk_hi, *qk_lo, *at_hi, *at_lo;
    cudaGetSymbolAddress((void**)&x_hi,  g_x_hi);
    cudaGetSymbolAddress((void**)&x_lo,  g_x_lo);
    cudaGetSymbolAddress((void**)&wq_h,  g_wqkv_h);
    cudaGetSymbolAddress((void**)&wo_h,  g_wout_h);
    cudaGetSymbolAddress((void**)&qk_hi, g_qkv_hi);
    cudaGetSymbolAddress((void**)&qk_lo, g_qkv_lo);
    cudaGetSymbolAddress((void**)&at_hi, g_att_hi);
    cudaGetSymbolAddress((void**)&at_lo, g_att_lo);

    cudaFuncSetAttribute(gemm_pre<true>,
                         cudaFuncAttributeMaxDynamicSharedMemorySize, GK2_SMEM);
    cudaFuncSetAttribute(gemm_pre<false>,
                         cudaFuncAttributeMaxDynamicSharedMemorySize, GK2_SMEM);
    cudaFuncSetAttribute(attn_mma,
                         cudaFuncAttributeMaxDynamicSharedMemorySize, AT_SMEM);

    split_all<<<XB + WQB + WOB, 256>>>(x, x_hi, x_lo, w_qkv, wq_h, w_out, wo_h);

    // QKV projection (fp16 2-term) -> Q fp16 hi/lo, K/V fp16 single
    gemm_pre<true><<<dim3(6144 / 128, 4096 / 128), 256, GK2_SMEM>>>(
        x_hi, x_lo, wq_h, b_qkv, nullptr, qk_hi, qk_lo,
        PB * PS, 3 * PD, PD);
    // Causal attention (fp16 asymmetric) -> fp16 hi/lo att
    attn_mma<<<dim3(PS / BQ, PB * PH), 256, AT_SMEM>>>(qk_hi, qk_lo, at_hi, at_lo);
    // Output projection (fp16 2-term) -> fp32 out
    gemm_pre<false><<<dim3(2048 / 128, 4096 / 128), 256, GK2_SMEM>>>(
        at_hi, at_lo, wo_h, b_out, out, nullptr, nullptr,
        PB * PS, PD, PD);
}

// round 17
// speedup vs baseline: 1.6479x; 1.1717x over previous
#include <cuda_runtime.h>
#include <cuda_bf16.h>
#include <cuda_fp16.h>
#include <cstdint>

#define PB 2
#define PS 2048
#define PD 2048
#define PH 16
#define PHD 128

typedef unsigned short u16;

// Scratch (device globals: allocation-free)
__device__ u16 g_x_hi[(size_t)PB * PS * PD];      // fp16
__device__ u16 g_x_lo[(size_t)PB * PS * PD];      // fp16
__device__ u16 g_wqkv_h[(size_t)PD * 3 * PD];     // fp16 (single)
__device__ u16 g_wout_h[(size_t)PD * PD];         // fp16 (single)
__device__ u16 g_qkv_h[(size_t)PB * PS * 3 * PD]; // q,k,v all single fp16
__device__ u16 g_att_hi[(size_t)PB * PS * PD];    // fp16 (out-proj A hi)
__device__ u16 g_att_lo[(size_t)PB * PS * PD];    // fp16 (out-proj A lo)

// ============================ helpers ======================================
__device__ __forceinline__ uint32_t smem_u32(const void* p) {
    uint32_t a;
    asm("{ .reg .u64 t; cvta.to.shared.u64 t, %1; cvt.u32.u64 %0, t; }"
        : "=r"(a) : "l"(p));
    return a;
}
__device__ __forceinline__ void ldm_x4(uint32_t* r, uint32_t addr) {
    asm volatile("ldmatrix.sync.aligned.m8n8.x4.shared.b16 {%0,%1,%2,%3}, [%4];"
                 : "=r"(r[0]), "=r"(r[1]), "=r"(r[2]), "=r"(r[3]) : "r"(addr));
}
__device__ __forceinline__ void ldm_x4_t(uint32_t* r, uint32_t addr) {
    asm volatile("ldmatrix.sync.aligned.m8n8.x4.trans.shared.b16 {%0,%1,%2,%3}, [%4];"
                 : "=r"(r[0]), "=r"(r[1]), "=r"(r[2]), "=r"(r[3]) : "r"(addr));
}
__device__ __forceinline__ void mma_f16(float* d, const uint32_t* a, const uint32_t* b) {
    asm volatile(
        "mma.sync.aligned.m16n8k16.row.col.f32.f16.f16.f32 "
        "{%0,%1,%2,%3}, {%4,%5,%6,%7}, {%8,%9}, {%0,%1,%2,%3};"
        : "+f"(d[0]), "+f"(d[1]), "+f"(d[2]), "+f"(d[3])
        : "r"(a[0]), "r"(a[1]), "r"(a[2]), "r"(a[3]), "r"(b[0]), "r"(b[1]));
}
__device__ __forceinline__ uint32_t pack2h(__half x, __half y) {
    uint16_t xr = *reinterpret_cast<uint16_t*>(&x);
    uint16_t yr = *reinterpret_cast<uint16_t*>(&y);
    return (uint32_t)xr | ((uint32_t)yr << 16);
}
__device__ __forceinline__ void split4h(float4 v, uint2& hi, uint2& lo) {
    __half h0 = __float2half_rn(v.x), h1 = __float2half_rn(v.y);
    __half h2 = __float2half_rn(v.z), h3 = __float2half_rn(v.w);
    float r0 = v.x - __half2float(h0);
    float r1 = v.y - __half2float(h1);
    float r2 = v.z - __half2float(h2);
    float r3 = v.w - __half2float(h3);
    hi = make_uint2(pack2h(h0, h1), pack2h(h2, h3));
    lo = make_uint2(pack2h(__float2half_rn(r0), __float2half_rn(r1)),
                    pack2h(__float2half_rn(r2), __float2half_rn(r3)));
}
__device__ __forceinline__ uint2 cvt4h(float4 v) {
    return make_uint2(pack2h(__float2half_rn(v.x), __float2half_rn(v.y)),
                      pack2h(__float2half_rn(v.z), __float2half_rn(v.w)));
}
__device__ __forceinline__ void packhl_h(float x, float y, uint32_t& hi, uint32_t& lo) {
    __half hx = __float2half_rn(x), hy = __float2half_rn(y);
    hi = pack2h(hx, hy);
    lo = pack2h(__float2half_rn(x - __half2float(hx)),
                __float2half_rn(y - __half2float(hy)));
}
__device__ __forceinline__ void cp16(uint32_t saddr, const void* gaddr) {
    asm volatile("cp.async.cg.shared.global [%0], [%1], 16;"
                 :: "r"(saddr), "l"(gaddr) : "memory");
}
#define CP_COMMIT() asm volatile("cp.async.commit_group;" ::: "memory")
#define CP_WAIT(n)  asm volatile("cp.async.wait_group %0;" :: "n"(n) : "memory")

// ============ fused input-format kernel (1 launch) ========================
#define XB   ((PB * PS * PD) / 1024)
#define WQB  ((PD * 3 * PD) / 1024)
#define WOB  ((PD * PD) / 1024)

__global__ void __launch_bounds__(256) split_all(
    const float* __restrict__ x,   u16* __restrict__ xh,  u16* __restrict__ xl,
    const float* __restrict__ wq,  u16* __restrict__ wqh,
    const float* __restrict__ wo,  u16* __restrict__ woh)
{
    int bid = blockIdx.x;
    if (bid < XB) {
        const size_t i = ((size_t)bid * 256 + threadIdx.x) * 4;
        float4 v = *(const float4*)(x + i);
        uint2 h, l;
        split4h(v, h, l);
        *(uint2*)&xh[i] = h;
        *(uint2*)&xl[i] = l;
    } else if (bid < XB + WQB) {
        const size_t i = ((size_t)(bid - XB) * 256 + threadIdx.x) * 4;
        *(uint2*)&wqh[i] = cvt4h(*(const float4*)(wq + i));
    } else {
        const size_t i = ((size_t)(bid - XB - WQB) * 256 + threadIdx.x) * 4;
        *(uint2*)&woh[i] = cvt4h(*(const float4*)(wo + i));
    }
}

// ====== fp16 GEMM: C = (Ah[+Al]) @ Bh (+bias), 3-stage, 2 blk/SM ==========
// QKV_MODE: Q cols (col0<PD) 2-term; K/V cols 1-term; epilogue single fp16.
// else: always 2-term, fp32 epilogue.
#define AROW2 80
#define BROW2 272
#define ATILE2 (128 * AROW2)
#define BTILE2 (32 * BROW2)
#define STAGE2 (2 * ATILE2 + BTILE2)         // 29184
#define GK2_SMEM (3 * STAGE2)                // 87552

template <bool QKV_MODE>
__global__ void __launch_bounds__(256, 2) gemm_pre(
    const u16* __restrict__ Ahi_g, const u16* __restrict__ Alo_g,
    const u16* __restrict__ Bh_g,
    const float* __restrict__ bias, float* __restrict__ C,
    u16* __restrict__ Ch,
    int M, int N, int K)
{
    extern __shared__ char smc[];
    const uint32_t sb = smem_u32(smc);
    const int tid = threadIdx.x, lane = tid & 31, wid = tid >> 5;
    const int row0 = blockIdx.y * 128, col0 = blockIdx.x * 128;
    const int m0 = (wid & 3) * 32, n0 = (wid >> 2) * 64;
    const int g = lane >> 3, lr = lane & 7;
    const bool two = !QKV_MODE || (col0 < PD);   // uniform per block

    float acc[2][8][4];
    #pragma unroll
    for (int i = 0; i < 2; i++)
        #pragma unroll
        for (int j = 0; j < 8; j++)
            #pragma unroll
            for (int q = 0; q < 4; q++) acc[i][j][q] = 0.f;

    auto LOADC = [&](int kc, int s) {
        const uint32_t sa = sb + (uint32_t)s * STAGE2;
        #pragma unroll
        for (int it = 0; it < 2; it++) {
            int e = tid + it * 256;
            int r = e >> 2, c16 = e & 3;
            uint32_t off = sa + r * AROW2 + c16 * 16;
            size_t gi = (size_t)(row0 + r) * K + kc + c16 * 8;
            cp16(off, Ahi_g + gi);
            if (two) cp16(off + ATILE2, Alo_g + gi);
        }
        #pragma unroll
        for (int it = 0; it < 2; it++) {
            int e = tid + it * 256;
            int k = e >> 4, c16 = e & 15;
            uint32_t off = sa + 2 * ATILE2 + k * BROW2 + c16 * 16;
            size_t gi = (size_t)(kc + k) * N + col0 + c16 * 8;
            cp16(off, Bh_g + gi);
        }
        CP_COMMIT();
    };

    auto MMAC = [&](int s) {
        const uint32_t Ah = sb + (uint32_t)s * STAGE2;
        const uint32_t Bh = Ah + 2 * ATILE2;
        #pragma unroll
        for (int ks = 0; ks < 2; ks++) {
            const int kb = ks * 16;
            uint32_t aH[2][4], aL[2][4];
            #pragma unroll
            for (int mt = 0; mt < 2; mt++) {
                uint32_t ad = Ah + (m0 + mt * 16 + lr + ((g & 1) << 3)) * AROW2
                                 + (kb + ((g >> 1) << 3)) * 2;
                ldm_x4(aH[mt], ad);
                if (two) ldm_x4(aL[mt], ad + ATILE2);
            }
            #pragma unroll
            for (int q = 0; q < 4; q++) {
                int kk = kb + lr + ((g & 1) << 3);
                uint32_t bd = Bh + kk * BROW2 + (n0 + q * 16 + ((g >> 1) << 3)) * 2;
                uint32_t tH[4];
                ldm_x4_t(tH, bd);
                #pragma unroll
                for (int mt = 0; mt < 2; mt++) {
                    mma_f16(acc[mt][2 * q],     aH[mt], tH);
                    mma_f16(acc[mt][2 * q + 1], aH[mt], tH + 2);
                    if (two) {
                        mma_f16(acc[mt][2 * q],     aL[mt], tH);
                        mma_f16(acc[mt][2 * q + 1], aL[mt], tH + 2);
                    }
                }
            }
        }
    };

    const int NCH = K >> 5;

    LOADC(0, 0);
    LOADC(32, 1);

    int s = 0;
    int sn = 2;
    for (int c = 0; c < NCH; c++) {
        if (c + 1 < NCH) { CP_WAIT(1); } else { CP_WAIT(0); }
        __syncthreads();
        if (c + 2 < NCH) LOADC((c + 2) << 5, sn);
        MMAC(s);
        s = (s == 2) ? 0 : s + 1;
        sn = (sn == 2) ? 0 : sn + 1;
    }

    #pragma unroll
    for (int mt = 0; mt < 2; mt++) {
        #pragma unroll
        for (int nt = 0; nt < 8; nt++) {
            const int r = row0 + m0 + mt * 16 + (lane >> 2);
            const int cc = col0 + n0 + nt * 8 + ((lane & 3) << 1);
            const float b0 = bias[cc], b1 = bias[cc + 1];
            float v00 = acc[mt][nt][0] + b0, v01 = acc[mt][nt][1] + b1;
            float v10 = acc[mt][nt][2] + b0, v11 = acc[mt][nt][3] + b1;
            if (QKV_MODE) {   // single fp16 everywhere (q,k,v)
                *(uint32_t*)&Ch[(size_t)r * N + cc] =
                    pack2h(__float2half_rn(v00), __float2half_rn(v01));
                *(uint32_t*)&Ch[(size_t)(r + 8) * N + cc] =
                    pack2h(__float2half_rn(v10), __float2half_rn(v11));
            } else {
                *(float2*)(C + (size_t)r * N + cc) = make_float2(v00, v01);
                *(float2*)(C + (size_t)(r + 8) * N + cc) = make_float2(v10, v11);
            }
        }
    }
}

// ======== Flash attention: all-single fp16 (Q,K,P,V), Q in registers ======
#define BQ 128
#define BK 64
#define TROW 272
#define KTILE (64 * TROW)                  // 17408
#define KVSTG (2 * KTILE)                  // 34816: K, V
#define AT_SMEM (3 * KVSTG)                // 104448

__global__ void __launch_bounds__(256, 1) attn_mma(
    const u16* __restrict__ qkv_h,
    u16* __restrict__ att_hi, u16* __restrict__ att_lo)
{
    extern __shared__ char smc[];
    const uint32_t sb = smem_u32(smc);
    const uint32_t sKV = sb;
    const uint32_t sQ  = sb + KVSTG;       // Q lands in stage 1

    const int qt = (int)gridDim.x - 1 - (int)blockIdx.x;
    const int bh = blockIdx.y;
    const int b  = bh >> 4;
    const int h  = bh & 15;
    const int q0 = qt * BQ;
    const int tid  = threadIdx.x;
    const int lane = tid & 31;
    const int wid  = tid >> 5;
    const int lr   = lane & 7;
    const int g    = lane >> 3;
    const int rl   = lane >> 2;
    const int cq   = (lane & 3) << 1;

    const size_t rs = 3 * PD;
    const size_t base = (size_t)b * PS * rs + (size_t)h * PHD;
    const u16* qp = qkv_h + base;
    const u16* kp = qp + PD;
    const u16* vp = qp + 2 * PD;

    auto load_kv = [&](int kt, int st) {
        const uint32_t sa = sKV + (uint32_t)st * KVSTG;
        const int k0 = kt * BK;
        #pragma unroll
        for (int it = 0; it < 4; it++) {
            int e = tid + it * 256;
            int r = e >> 4, c16 = e & 15;
            uint32_t koff = sa + r * TROW + c16 * 16;
            size_t gi = (size_t)(k0 + r) * rs + c16 * 8;
            cp16(koff, kp + gi);
            cp16(koff + KTILE, vp + gi);
        }
        CP_COMMIT();
    };

    // Q (single): 128 rows x 16 chunks, one group
    #pragma unroll
    for (int it = 0; it < 8; it++) {
        int e = tid + it * 256;
        int r = e >> 4, c16 = e & 15;
        uint32_t off = sQ + r * TROW + c16 * 16;
        size_t gi = (size_t)(q0 + r) * rs + c16 * 8;
        cp16(off, qp + gi);
    }
    CP_COMMIT();

    const int nkt = 2 * qt + 2;
    load_kv(0, 0);

    CP_WAIT(1);          // Q landed (kv0 in flight)
    __syncthreads();
    uint32_t qH[8][4];
    #pragma unroll
    for (int ks = 0; ks < 8; ks++) {
        const uint32_t ad = sQ + (wid * 16 + lr + ((g & 1) << 3)) * TROW
                               + (ks * 16 + ((g >> 1) << 3)) * 2;
        ldm_x4(qH[ks], ad);
    }
    __syncthreads();     // Q extracted; stage 1 reusable
    if (nkt > 1) load_kv(1, 1);

    float O[16][4];
    #pragma unroll
    for (int nt = 0; nt < 16; nt++)
        #pragma unroll
        for (int c = 0; c < 4; c++) O[nt][c] = 0.f;
    float m0r = -1e30f, m1r = -1e30f, l0r = 0.f, l1r = 0.f;
    const float scale = 0.08838834764831845f;
    const int row_g0 = q0 + wid * 16 + rl;
    const int row_g1 = row_g0 + 8;

    int st = 0;
    int sn = 2;
    for (int kt = 0; kt < nkt; kt++) {
        const int k0 = kt * BK;
        if (kt + 1 < nkt) { CP_WAIT(1); } else { CP_WAIT(0); }
        __syncthreads();
        if (kt + 2 < nkt) load_kv(kt + 2, sn);

        const uint32_t sKt = sKV + (uint32_t)st * KVSTG;
        const uint32_t sVt = sKt + KTILE;

        // ---- S = Q K^T, single fp16
        float S[8][4];
        #pragma unroll
        for (int j = 0; j < 8; j++)
            #pragma unroll
            for (int c = 0; c < 4; c++) S[j][c] = 0.f;

        #pragma unroll
        for (int ks = 0; ks < 8; ks++) {
            #pragma unroll
            for (int p = 0; p < 4; p++) {
                uint32_t kH[4];
                const uint32_t kd = sKt + (p * 16 + lr + ((g >> 1) << 3)) * TROW
                                        + (ks * 16 + ((g & 1) << 3)) * 2;
                ldm_x4(kH, kd);
                mma_f16(S[2 * p],     qH[ks], kH);
                mma_f16(S[2 * p + 1], qH[ks], kH + 2);
            }
        }

        // ---- scale + mask + online softmax
        const bool need_mask = (k0 + BK - 1 > q0);
        float mx0 = -1e30f, mx1 = -1e30f;
        #pragma unroll
        for (int j = 0; j < 8; j++) {
            #pragma unroll
            for (int c = 0; c < 4; c++) {
                float s = S[j][c] * scale;
                if (need_mask) {
                    const int col = k0 + j * 8 + cq + (c & 1);
                    const int row = (c < 2) ? row_g0 : row_g1;
                    if (col > row) s = -1e30f;
                }
                S[j][c] = s;
            }
            mx0 = fmaxf(mx0, fmaxf(S[j][0], S[j][1]));
            mx1 = fmaxf(mx1, fmaxf(S[j][2], S[j][3]));
        }
        #pragma unroll
        for (int off = 1; off <= 2; off <<= 1) {
            mx0 = fmaxf(mx0, __shfl_xor_sync(0xffffffffu, mx0, off));
            mx1 = fmaxf(mx1, __shfl_xor_sync(0xffffffffu, mx1, off));
        }
        const float nm0 = fmaxf(m0r, mx0), nm1 = fmaxf(m1r, mx1);
        const float al0 = __expf(m0r - nm0), al1 = __expf(m1r - nm1);
        float sum0 = 0.f, sum1 = 0.f;
        #pragma unroll
        for (int j = 0; j < 8; j++) {
            S[j][0] = __expf(S[j][0] - nm0);
            S[j][1] = __expf(S[j][1] - nm0);
            S[j][2] = __expf(S[j][2] - nm1);
            S[j][3] = __expf(S[j][3] - nm1);
            sum0 += S[j][0] + S[j][1];
            sum1 += S[j][2] + S[j][3];
        }
        #pragma unroll
        for (int off = 1; off <= 2; off <<= 1) {
            sum0 += __shfl_xor_sync(0xffffffffu, sum0, off);
            sum1 += __shfl_xor_sync(0xffffffffu, sum1, off);
        }
        l0r = l0r * al0 + sum0;
        l1r = l1r * al1 + sum1;
        m0r = nm0; m1r = nm1;
        #pragma unroll
        for (int nt = 0; nt < 16; nt++) {
            O[nt][0] *= al0; O[nt][1] *= al0;
            O[nt][2] *= al1; O[nt][3] *= al1;
        }

        // ---- O += P V, single fp16
        #pragma unroll
        for (int kk = 0; kk < 4; kk++) {
            uint32_t aP[4];
            const int j0 = 2 * kk, j1 = 2 * kk + 1;
            aP[0] = pack2h(__float2half_rn(S[j0][0]), __float2half_rn(S[j0][1]));
            aP[1] = pack2h(__float2half_rn(S[j0][2]), __float2half_rn(S[j0][3]));
            aP[2] = pack2h(__float2half_rn(S[j1][0]), __float2half_rn(S[j1][1]));
            aP[3] = pack2h(__float2half_rn(S[j1][2]), __float2half_rn(S[j1][3]));
            #pragma unroll
            for (int nq = 0; nq < 4; nq++) {
                uint32_t vH0[4], vH1[4];
                const uint32_t vd0 = sVt + (kk * 16 + lr + ((g & 1) << 3)) * TROW
                                         + ((2 * nq) * 16 + ((g >> 1) << 3)) * 2;
                ldm_x4_t(vH0, vd0);
                ldm_x4_t(vH1, vd0 + 32);
                mma_f16(O[4 * nq],     aP, vH0);
                mma_f16(O[4 * nq + 1], aP, vH0 + 2);
                mma_f16(O[4 * nq + 2], aP, vH1);
                mma_f16(O[4 * nq + 3], aP, vH1 + 2);
            }
        }
        st = (st == 2) ? 0 : st + 1;
        sn = (sn == 2) ? 0 : sn + 1;
    }

    // ---- normalize + fp16 hi/lo split-write (out-proj A operand)
    const float inv0 = 1.f / l0r, inv1 = 1.f / l1r;
    const size_t o0 = ((size_t)b * PS + row_g0) * PD + h * PHD;
    const size_t o1 = ((size_t)b * PS + row_g1) * PD + h * PHD;
    #pragma unroll
    for (int nt = 0; nt < 16; nt++) {
        const int col = nt * 8 + cq;
        uint32_t hh, ll;
        packhl_h(O[nt][0] * inv0, O[nt][1] * inv0, hh, ll);
        *(uint32_t*)&att_hi[o0 + col] = hh;
        *(uint32_t*)&att_lo[o0 + col] = ll;
        packhl_h(O[nt][2] * inv1, O[nt][3] * inv1, hh, ll);
        *(uint32_t*)&att_hi[o1 + col] = hh;
        *(uint32_t*)&att_lo[o1 + col] = ll;
    }
}

// ---------------------------------------------------------------------------
extern "C" void kernel_launch(void* const* d_in, const int* in_sizes, int n_in,
                              void* d_out, int out_size)
{
    const float* x     = (const float*)d_in[0];
    const float* w_qkv = (const float*)d_in[1];
    const float* b_qkv = (const float*)d_in[2];
    const float* w_out = (const float*)d_in[3];
    const float* b_out = (const float*)d_in[4];
    float* out = (float*)d_out;

    u16 *x_hi, *x_lo, *wq_h, *wo_h, *qk_h, *at_hi, *at_lo;
    cudaGetSymbolAddress((void**)&x_hi,  g_x_hi);
    cudaGetSymbolAddress((void**)&x_lo,  g_x_lo);
    cudaGetSymbolAddress((void**)&wq_h,  g_wqkv_h);
    cudaGetSymbolAddress((void**)&wo_h,  g_wout_h);
    cudaGetSymbolAddress((void**)&qk_h,  g_qkv_h);
    cudaGetSymbolAddress((void**)&at_hi, g_att_hi);
    cudaGetSymbolAddress((void**)&at_lo, g_att_lo);

    cudaFuncSetAttribute(gemm_pre<true>,
                         cudaFuncAttributeMaxDynamicSharedMemorySize, GK2_SMEM);
    cudaFuncSetAttribute(gemm_pre<false>,
                         cudaFuncAttributeMaxDynamicSharedMemorySize, GK2_SMEM);
    cudaFuncSetAttribute(attn_mma,
                         cudaFuncAttributeMaxDynamicSharedMemorySize, AT_SMEM);

    split_all<<<XB + WQB + WOB, 256>>>(x, x_hi, x_lo, w_qkv, wq_h, w_out, wo_h);

    // QKV projection: Q cols 2-term, K/V cols 1-term -> single fp16 qkv
    gemm_pre<true><<<dim3(6144 / 128, 4096 / 128), 256, GK2_SMEM>>>(
        x_hi, x_lo, wq_h, b_qkv, nullptr, qk_h,
        PB * PS, 3 * PD, PD);
    // Causal attention (all-single fp16) -> fp16 hi/lo att
    attn_mma<<<dim3(PS / BQ, PB * PH), 256, AT_SMEM>>>(qk_h, at_hi, at_lo);
    // Output projection (2-term) -> fp32 out
    gemm_pre<false><<<dim3(2048 / 128, 4096 / 128), 256, GK2_SMEM>>>(
        at_hi, at_lo, wo_h, b_out, out, nullptr,
        PB * PS, PD, PD);
}